// round 3
// baseline (speedup 1.0000x reference)
#include <cuda_runtime.h>
#include <cuda_bf16.h>

#define NP 4096
#define NL 2048
#define DM 512
#define NH 8
#define DK 64

// Scratch (allocation-free rule: __device__ globals)
__device__ float g_Q[NP * DM];
__device__ float g_K[NL * DM];
__device__ float g_V[NL * DM];
__device__ float g_ctx[NP * DM];
__device__ float g_tmp[NP * DM];
__device__ int   g_bp[NP];
__device__ int   g_bl[NL];

// ---------------------------------------------------------------------------
// Normalize batch arrays to int32, robust to the harness supplying either
// int32 or int64. Arrays are SORTED values in [0, 16): if dtype is int32 the
// int32 word at index n-1 is the max batch (15, nonzero); if int64 it is the
// high word of element (n-1)/2, which is 0.
// ---------------------------------------------------------------------------
__global__ void prep_batch(const int* __restrict__ raw, int n, int* __restrict__ out)
{
    __shared__ int is32;
    if (threadIdx.x == 0) is32 = (raw[n - 1] != 0) ? 1 : 0;
    __syncthreads();
    for (int i = blockIdx.x * blockDim.x + threadIdx.x; i < n; i += gridDim.x * blockDim.x)
        out[i] = is32 ? raw[i] : raw[2 * i];
}

// ---------------------------------------------------------------------------
// Y[n][m] = sum_k X[n][k] * W[m][k] + bias[m] (+ res[n][m])
// N rows (multiple of 64), K = M = 512. Block tile 64x64, thread 4x4.
// ---------------------------------------------------------------------------
__global__ void gemm_nt_bias(const float* __restrict__ X,
                             const float* __restrict__ W,
                             const float* __restrict__ bias,
                             const float* __restrict__ res,
                             float* __restrict__ Y)
{
    const int BK = 16;
    __shared__ float Xs[64][BK + 1];
    __shared__ float Ws[64][BK + 1];

    const int row0 = blockIdx.y * 64;
    const int col0 = blockIdx.x * 64;
    const int t  = threadIdx.x;
    const int tx = t & 15;
    const int ty = t >> 4;

    float acc[4][4] = {};

    const int lr = t >> 2;
    const int lq = t & 3;

    for (int k0 = 0; k0 < DM; k0 += BK) {
        float4 xv = *reinterpret_cast<const float4*>(&X[(size_t)(row0 + lr) * DM + k0 + lq * 4]);
        Xs[lr][lq * 4 + 0] = xv.x; Xs[lr][lq * 4 + 1] = xv.y;
        Xs[lr][lq * 4 + 2] = xv.z; Xs[lr][lq * 4 + 3] = xv.w;
        float4 wv = *reinterpret_cast<const float4*>(&W[(size_t)(col0 + lr) * DM + k0 + lq * 4]);
        Ws[lr][lq * 4 + 0] = wv.x; Ws[lr][lq * 4 + 1] = wv.y;
        Ws[lr][lq * 4 + 2] = wv.z; Ws[lr][lq * 4 + 3] = wv.w;
        __syncthreads();

        #pragma unroll
        for (int kk = 0; kk < BK; kk++) {
            float a[4], b[4];
            #pragma unroll
            for (int i = 0; i < 4; i++) a[i] = Xs[ty * 4 + i][kk];
            #pragma unroll
            for (int j = 0; j < 4; j++) b[j] = Ws[tx * 4 + j][kk];
            #pragma unroll
            for (int i = 0; i < 4; i++)
                #pragma unroll
                for (int j = 0; j < 4; j++)
                    acc[i][j] += a[i] * b[j];
        }
        __syncthreads();
    }

    #pragma unroll
    for (int i = 0; i < 4; i++) {
        const int r = row0 + ty * 4 + i;
        #pragma unroll
        for (int j = 0; j < 4; j++) {
            const int c = col0 + tx * 4 + j;
            float v = acc[i][j] + bias[c];
            if (res) v += res[(size_t)r * DM + c];
            Y[(size_t)r * DM + c] = v;
        }
    }
}

// ---------------------------------------------------------------------------
// Fused attention: per CTA = (head h, 8 query rows).
// Scores kept in SMEM (8x2048 fp32), masked, softmaxed, written once to
// d_out's attn region, then consumed for the PV context accumulation.
// Context written in the scrambled layout of transpose(0,1).view(-1,512):
// flat offset = (h*NP + p)*64 + d.
// ---------------------------------------------------------------------------
__global__ void attn_kernel(const float* __restrict__ Q,
                            const float* __restrict__ Km,
                            const float* __restrict__ Vm,
                            const int* __restrict__ bp,
                            const int* __restrict__ bl,
                            float* __restrict__ attn,
                            float* __restrict__ ctx)
{
    extern __shared__ float sm[];
    float* sQ  = sm;                 // 8 * 64
    float* sKV = sm + 8 * 64;        // 64 * 65 (K chunk, reused for V chunk)
    float* sP  = sKV + 64 * 65;      // 8 * 2048

    const int h  = blockIdx.y;
    const int p0 = blockIdx.x * 8;
    const int t  = threadIdx.x;
    const int r    = t >> 5;         // warp = row (0..7)
    const int lane = t & 31;

    for (int i = t; i < 8 * 64; i += 256) {
        const int rr = i >> 6, d = i & 63;
        sQ[i] = Q[(size_t)(p0 + rr) * DM + h * 64 + d];
    }
    __syncthreads();

    const int bprow = bp[p0 + r];
    const float scale = 0.125f;      // 1/sqrt(64)

    // ---- scores: loop K in chunks of 64 keys ----
    for (int l0 = 0; l0 < NL; l0 += 64) {
        for (int i = t; i < 64 * 64; i += 256) {
            const int lr2 = i >> 6, d = i & 63;
            sKV[lr2 * 65 + d] = Km[(size_t)(l0 + lr2) * DM + h * 64 + d];
        }
        __syncthreads();
        #pragma unroll
        for (int half = 0; half < 2; half++) {
            const int lc = lane + half * 32;
            float s = 0.f;
            #pragma unroll
            for (int k = 0; k < 64; k++)
                s += sQ[r * 64 + k] * sKV[lc * 65 + k];
            s *= scale;
            if (bl[l0 + lc] != bprow) s = -1e9f;
            sP[r * 2048 + l0 + lc] = s;
        }
        __syncthreads();
    }

    // ---- softmax per row (warp-local) ----
    float mx = -1e30f;
    for (int l = lane; l < NL; l += 32) mx = fmaxf(mx, sP[r * 2048 + l]);
    #pragma unroll
    for (int o = 16; o; o >>= 1) mx = fmaxf(mx, __shfl_xor_sync(0xffffffffu, mx, o));
    float sum = 0.f;
    for (int l = lane; l < NL; l += 32) {
        const float e = __expf(sP[r * 2048 + l] - mx);
        sP[r * 2048 + l] = e;
        sum += e;
    }
    #pragma unroll
    for (int o = 16; o; o >>= 1) sum += __shfl_xor_sync(0xffffffffu, sum, o);
    const float inv = 1.f / sum;

    float* attn_row = attn + ((size_t)h * NP + (p0 + r)) * NL;
    for (int l = lane; l < NL; l += 32) {
        const float pv = sP[r * 2048 + l] * inv;
        sP[r * 2048 + l] = pv;
        attn_row[l] = pv;
    }

    // ---- context: ctx_flat[h][p][d] = sum_l P[p][l] * V[l][d] ----
    float acc0 = 0.f, acc1 = 0.f;
    for (int l0 = 0; l0 < NL; l0 += 64) {
        __syncthreads();
        for (int i = t; i < 64 * 64; i += 256) {
            const int lr2 = i >> 6, d = i & 63;
            sKV[lr2 * 65 + d] = Vm[(size_t)(l0 + lr2) * DM + h * 64 + d];
        }
        __syncthreads();
        #pragma unroll
        for (int l = 0; l < 64; l++) {
            const float pv = sP[r * 2048 + l0 + l];
            acc0 += pv * sKV[l * 65 + lane];
            acc1 += pv * sKV[l * 65 + lane + 32];
        }
    }
    ctx[((size_t)h * NP + (p0 + r)) * 64 + lane]      = acc0;
    ctx[((size_t)h * NP + (p0 + r)) * 64 + lane + 32] = acc1;
}

// ---------------------------------------------------------------------------
// LayerNorm: warp per row over 512 features.
// ---------------------------------------------------------------------------
__global__ void ln_kernel(const float* __restrict__ X,
                          const float* __restrict__ gamma,
                          const float* __restrict__ beta,
                          float* __restrict__ out)
{
    const int row  = blockIdx.x * 8 + (threadIdx.x >> 5);
    const int lane = threadIdx.x & 31;
    const float* xr = X + (size_t)row * DM;

    float v[16];
    float s = 0.f;
    #pragma unroll
    for (int i = 0; i < 16; i++) { v[i] = xr[lane + i * 32]; s += v[i]; }
    #pragma unroll
    for (int o = 16; o; o >>= 1) s += __shfl_xor_sync(0xffffffffu, s, o);
    const float mu = s * (1.f / 512.f);

    float q = 0.f;
    #pragma unroll
    for (int i = 0; i < 16; i++) { const float d = v[i] - mu; q += d * d; }
    #pragma unroll
    for (int o = 16; o; o >>= 1) q += __shfl_xor_sync(0xffffffffu, q, o);
    const float rstd = rsqrtf(q * (1.f / 512.f) + 1e-5f);

    #pragma unroll
    for (int i = 0; i < 16; i++) {
        const int c = lane + i * 32;
        out[(size_t)row * DM + c] = (v[i] - mu) * rstd * gamma[c] + beta[c];
    }
}

// ---------------------------------------------------------------------------
extern "C" void kernel_launch(void* const* d_in, const int* in_sizes, int n_in,
                              void* d_out, int out_size)
{
    const float* protein = (const float*)d_in[0];
    const float* ligand  = (const float*)d_in[1];
    const int* bp_raw    = (const int*)d_in[2];
    const int* bl_raw    = (const int*)d_in[3];
    const float* Wq = (const float*)d_in[4];
    const float* bq = (const float*)d_in[5];
    const float* Wk = (const float*)d_in[6];
    const float* bk = (const float*)d_in[7];
    const float* Wv = (const float*)d_in[8];
    const float* bv = (const float*)d_in[9];
    const float* Wo = (const float*)d_in[10];
    const float* bo = (const float*)d_in[11];
    const float* gamma = (const float*)d_in[12];
    const float* beta  = (const float*)d_in[13];

    float* out  = (float*)d_out;                      // [4096, 512]
    float* attn = out + (size_t)NP * DM;              // [1, 8, 4096, 2048]

    float *Qp, *Kp, *Vp, *Cp, *Tp;
    int *bpp, *blp;
    cudaGetSymbolAddress((void**)&Qp, g_Q);
    cudaGetSymbolAddress((void**)&Kp, g_K);
    cudaGetSymbolAddress((void**)&Vp, g_V);
    cudaGetSymbolAddress((void**)&Cp, g_ctx);
    cudaGetSymbolAddress((void**)&Tp, g_tmp);
    cudaGetSymbolAddress((void**)&bpp, g_bp);
    cudaGetSymbolAddress((void**)&blp, g_bl);

    const int attn_smem = (8 * 64 + 64 * 65 + 8 * 2048) * (int)sizeof(float); // 84224
    cudaFuncSetAttribute(attn_kernel, cudaFuncAttributeMaxDynamicSharedMemorySize, attn_smem);

    // Batch arrays -> int32 (robust to int32/int64 harness dtype)
    prep_batch<<<8, 256>>>(bp_raw, NP, bpp);
    prep_batch<<<8, 256>>>(bl_raw, NL, blp);

    // Projections
    gemm_nt_bias<<<dim3(8, NP / 64), 256>>>(protein, Wq, bq, nullptr, Qp);
    gemm_nt_bias<<<dim3(8, NL / 64), 256>>>(ligand,  Wk, bk, nullptr, Kp);
    gemm_nt_bias<<<dim3(8, NL / 64), 256>>>(ligand,  Wv, bv, nullptr, Vp);

    // Fused attention (scores + mask + softmax + attn write + context)
    attn_kernel<<<dim3(NP / 8, NH), 256, attn_smem>>>(Qp, Kp, Vp, bpp, blp, attn, Cp);

    // Output projection + residual, then LayerNorm
    gemm_nt_bias<<<dim3(8, NP / 64), 256>>>(Cp, Wo, bo, protein, Tp);
    ln_kernel<<<NP / 8, 256>>>(Tp, gamma, beta, out);
}

// round 4
// speedup vs baseline: 4.0952x; 4.0952x over previous
#include <cuda_runtime.h>
#include <cuda_bf16.h>

#define NP 4096
#define NL 2048
#define DM 512
#define NH 8
#define DK 64

// Scratch (allocation-free rule: __device__ globals)
__device__ float g_Q[NP * DM];
__device__ float g_K[NL * DM];
__device__ float g_V[NL * DM];
__device__ float g_ctx[NP * DM];
__device__ float g_tmp[NP * DM];
__device__ int   g_bp[NP];
__device__ int   g_bl[NL];
__device__ int   g_lstart[16];
__device__ int   g_lend[16];

// ---------------------------------------------------------------------------
// Normalize batch arrays to int32 (robust to int32/int64 harness dtype).
// Arrays are SORTED values in [0,16): int32 word at index n-1 is 15 (nonzero)
// if dtype==int32; it is a zero high word if dtype==int64.
// ---------------------------------------------------------------------------
__global__ void prep_batch(const int* __restrict__ raw, int n, int* __restrict__ out)
{
    __shared__ int is32;
    if (threadIdx.x == 0) is32 = (raw[n - 1] != 0) ? 1 : 0;
    __syncthreads();
    for (int i = blockIdx.x * blockDim.x + threadIdx.x; i < n; i += gridDim.x * blockDim.x)
        out[i] = is32 ? raw[i] : raw[2 * i];
}

// Per-batch contiguous key ranges from the sorted ligand batch array.
__global__ void prep_ranges(const int* __restrict__ bl, int n)
{
    const int t = threadIdx.x;
    if (t < 16) { g_lstart[t] = 0; g_lend[t] = 0; }
    __syncthreads();
    for (int i = t; i < n; i += blockDim.x) {
        const int b = bl[i];
        if (i == 0 || bl[i - 1] != b) g_lstart[b] = i;
        if (i == n - 1 || bl[i + 1] != b) g_lend[b] = i + 1;
    }
}

// Zero-fill the attn output (masked entries are exactly 0.0 after softmax).
__global__ void zero_attn(float4* __restrict__ p, int n4)
{
    int i = blockIdx.x * blockDim.x + threadIdx.x;
    const int stride = gridDim.x * blockDim.x;
    const float4 z = make_float4(0.f, 0.f, 0.f, 0.f);
    for (; i < n4; i += stride) p[i] = z;
}

// ---------------------------------------------------------------------------
// Y[n][m] = sum_k X[n][k] * W[m][k] + bias[m] (+ res[n][m])
// ---------------------------------------------------------------------------
__global__ void gemm_nt_bias(const float* __restrict__ X,
                             const float* __restrict__ W,
                             const float* __restrict__ bias,
                             const float* __restrict__ res,
                             float* __restrict__ Y)
{
    const int BK = 16;
    __shared__ float Xs[64][BK + 1];
    __shared__ float Ws[64][BK + 1];

    const int row0 = blockIdx.y * 64;
    const int col0 = blockIdx.x * 64;
    const int t  = threadIdx.x;
    const int tx = t & 15;
    const int ty = t >> 4;

    float acc[4][4] = {};

    const int lr = t >> 2;
    const int lq = t & 3;

    for (int k0 = 0; k0 < DM; k0 += BK) {
        float4 xv = *reinterpret_cast<const float4*>(&X[(size_t)(row0 + lr) * DM + k0 + lq * 4]);
        Xs[lr][lq * 4 + 0] = xv.x; Xs[lr][lq * 4 + 1] = xv.y;
        Xs[lr][lq * 4 + 2] = xv.z; Xs[lr][lq * 4 + 3] = xv.w;
        float4 wv = *reinterpret_cast<const float4*>(&W[(size_t)(col0 + lr) * DM + k0 + lq * 4]);
        Ws[lr][lq * 4 + 0] = wv.x; Ws[lr][lq * 4 + 1] = wv.y;
        Ws[lr][lq * 4 + 2] = wv.z; Ws[lr][lq * 4 + 3] = wv.w;
        __syncthreads();

        #pragma unroll
        for (int kk = 0; kk < BK; kk++) {
            float a[4], b[4];
            #pragma unroll
            for (int i = 0; i < 4; i++) a[i] = Xs[ty * 4 + i][kk];
            #pragma unroll
            for (int j = 0; j < 4; j++) b[j] = Ws[tx * 4 + j][kk];
            #pragma unroll
            for (int i = 0; i < 4; i++)
                #pragma unroll
                for (int j = 0; j < 4; j++)
                    acc[i][j] += a[i] * b[j];
        }
        __syncthreads();
    }

    #pragma unroll
    for (int i = 0; i < 4; i++) {
        const int r = row0 + ty * 4 + i;
        #pragma unroll
        for (int j = 0; j < 4; j++) {
            const int c = col0 + tx * 4 + j;
            float v = acc[i][j] + bias[c];
            if (res) v += res[(size_t)r * DM + c];
            Y[(size_t)r * DM + c] = v;
        }
    }
}

// ---------------------------------------------------------------------------
// Fused attention, batch-range aware: per CTA = (head h, 8 query rows).
// Only key chunks intersecting the union of the rows' batch ranges are
// processed (sorted batches => contiguous ranges). Everything outside is
// exactly 0 in the reference (exp(-1e9 - mx) underflows) and is handled by
// the zero_attn pre-fill.
// ---------------------------------------------------------------------------
__global__ void attn_kernel(const float* __restrict__ Q,
                            const float* __restrict__ Km,
                            const float* __restrict__ Vm,
                            const int* __restrict__ bp,
                            const int* __restrict__ bl,
                            float* __restrict__ attn,
                            float* __restrict__ ctx)
{
    extern __shared__ float sm[];
    float* sQ  = sm;                 // 8 * 64
    float* sKV = sm + 8 * 64;        // 64 * 65 (K chunk, reused for V chunk)
    float* sP  = sKV + 64 * 65;      // 8 * 2048
    __shared__ int s_rs[8], s_re[8];

    const int h  = blockIdx.y;
    const int p0 = blockIdx.x * 8;
    const int t  = threadIdx.x;
    const int r    = t >> 5;         // warp = row (0..7)
    const int lane = t & 31;

    for (int i = t; i < 8 * 64; i += 256) {
        const int rr = i >> 6, d = i & 63;
        sQ[i] = Q[(size_t)(p0 + rr) * DM + h * 64 + d];
    }

    const int bprow = bp[p0 + r];
    if (lane == 0) { s_rs[r] = g_lstart[bprow]; s_re[r] = g_lend[bprow]; }
    __syncthreads();

    int u_lo = s_rs[0], u_hi = s_re[0];
    #pragma unroll
    for (int i = 1; i < 8; i++) { u_lo = min(u_lo, s_rs[i]); u_hi = max(u_hi, s_re[i]); }
    const int l_lo = u_lo & ~63;                       // chunk-aligned start
    const int l_hi = u_hi;                             // exclusive end
    const int reg_hi = min(NL, (l_hi + 63) & ~63);     // end of stored sP region

    const float scale = 0.125f;      // 1/sqrt(64)

    // ---- scores over in-range key chunks ----
    for (int l0 = l_lo; l0 < l_hi; l0 += 64) {
        for (int i = t; i < 64 * 64; i += 256) {
            const int lr2 = i >> 6, d = i & 63;
            sKV[lr2 * 65 + d] = Km[(size_t)(l0 + lr2) * DM + h * 64 + d];
        }
        __syncthreads();
        #pragma unroll
        for (int half = 0; half < 2; half++) {
            const int lc = lane + half * 32;
            float s = 0.f;
            #pragma unroll
            for (int k = 0; k < 64; k++)
                s += sQ[r * 64 + k] * sKV[lc * 65 + k];
            s *= scale;
            if (bl[l0 + lc] != bprow) s = -1e9f;
            sP[r * 2048 + l0 + lc] = s;
        }
        __syncthreads();
    }

    // ---- softmax per row (warp-local), over the stored region only ----
    float mx = -1e30f;
    for (int l = l_lo + lane; l < reg_hi; l += 32) mx = fmaxf(mx, sP[r * 2048 + l]);
    #pragma unroll
    for (int o = 16; o; o >>= 1) mx = fmaxf(mx, __shfl_xor_sync(0xffffffffu, mx, o));
    float sum = 0.f;
    for (int l = l_lo + lane; l < reg_hi; l += 32) {
        const float e = __expf(sP[r * 2048 + l] - mx);
        sP[r * 2048 + l] = e;
        sum += e;
    }
    #pragma unroll
    for (int o = 16; o; o >>= 1) sum += __shfl_xor_sync(0xffffffffu, sum, o);
    const float inv = 1.f / sum;

    float* attn_row = attn + ((size_t)h * NP + (p0 + r)) * NL;
    for (int l = l_lo + lane; l < reg_hi; l += 32) {
        const float pv = sP[r * 2048 + l] * inv;
        sP[r * 2048 + l] = pv;
        attn_row[l] = pv;
    }

    // ---- context over in-range chunks: ctx_flat[h][p][d] = sum_l P*V ----
    float acc0 = 0.f, acc1 = 0.f;
    for (int l0 = l_lo; l0 < l_hi; l0 += 64) {
        __syncthreads();
        for (int i = t; i < 64 * 64; i += 256) {
            const int lr2 = i >> 6, d = i & 63;
            sKV[lr2 * 65 + d] = Vm[(size_t)(l0 + lr2) * DM + h * 64 + d];
        }
        __syncthreads();
        #pragma unroll
        for (int l = 0; l < 64; l++) {
            const float pv = sP[r * 2048 + l0 + l];
            acc0 += pv * sKV[l * 65 + lane];
            acc1 += pv * sKV[l * 65 + lane + 32];
        }
    }
    // Scrambled layout of transpose(0,1).contiguous().view(-1, 512)
    ctx[((size_t)h * NP + (p0 + r)) * 64 + lane]      = acc0;
    ctx[((size_t)h * NP + (p0 + r)) * 64 + lane + 32] = acc1;
}

// ---------------------------------------------------------------------------
// LayerNorm: warp per row over 512 features.
// ---------------------------------------------------------------------------
__global__ void ln_kernel(const float* __restrict__ X,
                          const float* __restrict__ gamma,
                          const float* __restrict__ beta,
                          float* __restrict__ out)
{
    const int row  = blockIdx.x * 8 + (threadIdx.x >> 5);
    const int lane = threadIdx.x & 31;
    const float* xr = X + (size_t)row * DM;

    float v[16];
    float s = 0.f;
    #pragma unroll
    for (int i = 0; i < 16; i++) { v[i] = xr[lane + i * 32]; s += v[i]; }
    #pragma unroll
    for (int o = 16; o; o >>= 1) s += __shfl_xor_sync(0xffffffffu, s, o);
    const float mu = s * (1.f / 512.f);

    float q = 0.f;
    #pragma unroll
    for (int i = 0; i < 16; i++) { const float d = v[i] - mu; q += d * d; }
    #pragma unroll
    for (int o = 16; o; o >>= 1) q += __shfl_xor_sync(0xffffffffu, q, o);
    const float rstd = rsqrtf(q * (1.f / 512.f) + 1e-5f);

    #pragma unroll
    for (int i = 0; i < 16; i++) {
        const int c = lane + i * 32;
        out[(size_t)row * DM + c] = (v[i] - mu) * rstd * gamma[c] + beta[c];
    }
}

// ---------------------------------------------------------------------------
extern "C" void kernel_launch(void* const* d_in, const int* in_sizes, int n_in,
                              void* d_out, int out_size)
{
    const float* protein = (const float*)d_in[0];
    const float* ligand  = (const float*)d_in[1];
    const int* bp_raw    = (const int*)d_in[2];
    const int* bl_raw    = (const int*)d_in[3];
    const float* Wq = (const float*)d_in[4];
    const float* bq = (const float*)d_in[5];
    const float* Wk = (const float*)d_in[6];
    const float* bk = (const float*)d_in[7];
    const float* Wv = (const float*)d_in[8];
    const float* bv = (const float*)d_in[9];
    const float* Wo = (const float*)d_in[10];
    const float* bo = (const float*)d_in[11];
    const float* gamma = (const float*)d_in[12];
    const float* beta  = (const float*)d_in[13];

    float* out  = (float*)d_out;                      // [4096, 512]
    float* attn = out + (size_t)NP * DM;              // [1, 8, 4096, 2048]

    float *Qp, *Kp, *Vp, *Cp, *Tp;
    int *bpp, *blp;
    cudaGetSymbolAddress((void**)&Qp, g_Q);
    cudaGetSymbolAddress((void**)&Kp, g_K);
    cudaGetSymbolAddress((void**)&Vp, g_V);
    cudaGetSymbolAddress((void**)&Cp, g_ctx);
    cudaGetSymbolAddress((void**)&Tp, g_tmp);
    cudaGetSymbolAddress((void**)&bpp, g_bp);
    cudaGetSymbolAddress((void**)&blp, g_bl);

    const int attn_smem = (8 * 64 + 64 * 65 + 8 * 2048) * (int)sizeof(float); // 84224
    cudaFuncSetAttribute(attn_kernel, cudaFuncAttributeMaxDynamicSharedMemorySize, attn_smem);

    // Batch arrays -> int32, per-batch key ranges
    prep_batch<<<8, 256>>>(bp_raw, NP, bpp);
    prep_batch<<<8, 256>>>(bl_raw, NL, blp);
    prep_ranges<<<1, 256>>>(blp, NL);

    // Zero the attn output (covers all masked positions exactly)
    zero_attn<<<8192, 256>>>((float4*)attn, (int)(((size_t)NH * NP * NL) / 4));

    // Projections
    gemm_nt_bias<<<dim3(8, NP / 64), 256>>>(protein, Wq, bq, nullptr, Qp);
    gemm_nt_bias<<<dim3(8, NL / 64), 256>>>(ligand,  Wk, bk, nullptr, Kp);
    gemm_nt_bias<<<dim3(8, NL / 64), 256>>>(ligand,  Wv, bv, nullptr, Vp);

    // Fused attention over in-batch key ranges only
    attn_kernel<<<dim3(NP / 8, NH), 256, attn_smem>>>(Qp, Kp, Vp, bpp, blp, attn, Cp);

    // Output projection + residual, then LayerNorm
    gemm_nt_bias<<<dim3(8, NP / 64), 256>>>(Cp, Wo, bo, protein, Tp);
    ln_kernel<<<NP / 8, 256>>>(Tp, gamma, beta, out);
}

// round 6
// speedup vs baseline: 5.5380x; 1.3523x over previous
#include <cuda_runtime.h>
#include <cuda_bf16.h>

#define NP 4096
#define NL 2048
#define DM 512
#define NH 8
#define DK 64
#define NB 16
#define MAXT 80   // max row tiles: 4096/64 + 16

// Scratch (allocation-free rule: __device__ globals)
__device__ float g_Q[NP * DM];
__device__ float g_K[NL * DM];
__device__ float g_V[NL * DM];
__device__ float g_ctx[NP * DM];
__device__ float g_tmp[NP * DM];
__device__ int   g_bp[NP];
__device__ int   g_bl[NL];
__device__ int   g_pstart[NB], g_pend[NB];
__device__ int   g_lstart[NB], g_lend[NB];
__device__ int   g_tile_b[MAXT], g_tile_r[MAXT];

// ---------------------------------------------------------------------------
// Normalize batch arrays to int32 (robust to int32/int64 harness dtype).
// ---------------------------------------------------------------------------
__global__ void prep_batch(const int* __restrict__ raw, int n, int* __restrict__ out)
{
    __shared__ int is32;
    if (threadIdx.x == 0) is32 = (raw[n - 1] != 0) ? 1 : 0;
    __syncthreads();
    for (int i = blockIdx.x * blockDim.x + threadIdx.x; i < n; i += gridDim.x * blockDim.x)
        out[i] = is32 ? raw[i] : raw[2 * i];
}

// Per-batch contiguous ranges (sorted arrays) + row-tile worklist.
__global__ void prep_meta(const int* __restrict__ bp, const int* __restrict__ bl)
{
    const int t = threadIdx.x;
    if (t < NB) { g_pstart[t] = 0; g_pend[t] = 0; g_lstart[t] = 0; g_lend[t] = 0; }
    __syncthreads();
    for (int i = t; i < NP; i += blockDim.x) {
        const int b = bp[i];
        if (i == 0 || bp[i - 1] != b) g_pstart[b] = i;
        if (i == NP - 1 || bp[i + 1] != b) g_pend[b] = i + 1;
    }
    for (int i = t; i < NL; i += blockDim.x) {
        const int b = bl[i];
        if (i == 0 || bl[i - 1] != b) g_lstart[b] = i;
        if (i == NL - 1 || bl[i + 1] != b) g_lend[b] = i + 1;
    }
    __syncthreads();
    if (t == 0) {
        int idx = 0;
        for (int b = 0; b < NB; b++)
            for (int r = g_pstart[b]; r < g_pend[b]; r += 64) {
                g_tile_b[idx] = b; g_tile_r[idx] = r; idx++;
            }
        for (; idx < MAXT; idx++) g_tile_b[idx] = -1;
    }
}

// Zero-fill the attn output (masked entries are exactly 0.0 after softmax).
__global__ void zero_attn(float4* __restrict__ p, int n4)
{
    int i = blockIdx.x * blockDim.x + threadIdx.x;
    const int stride = gridDim.x * blockDim.x;
    const float4 z = make_float4(0.f, 0.f, 0.f, 0.f);
    for (; i < n4; i += stride) p[i] = z;
}

// ---------------------------------------------------------------------------
// Projection GEMM: Y[n][m] = sum_k X[n][k]*W[m][k] + bias[m] (+ res)
// ---------------------------------------------------------------------------
__global__ void gemm_nt_bias(const float* __restrict__ X,
                             const float* __restrict__ W,
                             const float* __restrict__ bias,
                             const float* __restrict__ res,
                             float* __restrict__ Y)
{
    const int BK = 16;
    __shared__ float Xs[64][BK + 1];
    __shared__ float Ws[64][BK + 1];

    const int row0 = blockIdx.y * 64;
    const int col0 = blockIdx.x * 64;
    const int t  = threadIdx.x;
    const int tx = t & 15;
    const int ty = t >> 4;

    float acc[4][4] = {};
    const int lr = t >> 2;
    const int lq = t & 3;

    for (int k0 = 0; k0 < DM; k0 += BK) {
        float4 xv = *reinterpret_cast<const float4*>(&X[(size_t)(row0 + lr) * DM + k0 + lq * 4]);
        Xs[lr][lq * 4 + 0] = xv.x; Xs[lr][lq * 4 + 1] = xv.y;
        Xs[lr][lq * 4 + 2] = xv.z; Xs[lr][lq * 4 + 3] = xv.w;
        float4 wv = *reinterpret_cast<const float4*>(&W[(size_t)(col0 + lr) * DM + k0 + lq * 4]);
        Ws[lr][lq * 4 + 0] = wv.x; Ws[lr][lq * 4 + 1] = wv.y;
        Ws[lr][lq * 4 + 2] = wv.z; Ws[lr][lq * 4 + 3] = wv.w;
        __syncthreads();

        #pragma unroll
        for (int kk = 0; kk < BK; kk++) {
            float a[4], b[4];
            #pragma unroll
            for (int i = 0; i < 4; i++) a[i] = Xs[ty * 4 + i][kk];
            #pragma unroll
            for (int j = 0; j < 4; j++) b[j] = Ws[tx * 4 + j][kk];
            #pragma unroll
            for (int i = 0; i < 4; i++)
                #pragma unroll
                for (int j = 0; j < 4; j++)
                    acc[i][j] += a[i] * b[j];
        }
        __syncthreads();
    }

    #pragma unroll
    for (int i = 0; i < 4; i++) {
        const int r = row0 + ty * 4 + i;
        #pragma unroll
        for (int j = 0; j < 4; j++) {
            const int c = col0 + tx * 4 + j;
            float v = acc[i][j] + bias[c];
            if (res) v += res[(size_t)r * DM + c];
            Y[(size_t)r * DM + c] = v;
        }
    }
}

// ---------------------------------------------------------------------------
// Scores: per (row-tile, head). S[p][l] = 0.125 * Q[p,:] . K[l,:]
// Dense within the batch rectangle — no mask checks needed.
// Scalar smem reads only (row stride 65 floats is NOT 16B aligned).
// ---------------------------------------------------------------------------
__global__ void score_kernel(const float* __restrict__ Q,
                             const float* __restrict__ Km,
                             float* __restrict__ attn)
{
    const int b = g_tile_b[blockIdx.x];
    if (b < 0) return;
    const int r0 = g_tile_r[blockIdx.x];
    const int nr = min(64, g_pend[b] - r0);
    const int l0 = g_lstart[b], l1 = g_lend[b];
    const int h  = blockIdx.y;

    __shared__ float Qs[64][65];   // [row][k] (pre-scaled)
    __shared__ float Ks[64][65];   // [col][k]

    const int t  = threadIdx.x;
    const int tx = t & 15;
    const int ty = t >> 4;

    for (int i = t; i < 64 * 64; i += 256) {
        const int row = i >> 6, d = i & 63;
        Qs[row][d] = (row < nr) ? Q[(size_t)(r0 + row) * DM + h * 64 + d] * 0.125f : 0.f;
    }

    for (int lc = l0; lc < l1; lc += 64) {
        for (int i = t; i < 64 * 64; i += 256) {
            const int col = i >> 6, d = i & 63;
            Ks[col][d] = (lc + col < l1) ? Km[(size_t)(lc + col) * DM + h * 64 + d] : 0.f;
        }
        __syncthreads();

        float acc[4][4] = {};
        #pragma unroll
        for (int k = 0; k < 64; k++) {
            float av[4], bv[4];
            #pragma unroll
            for (int i = 0; i < 4; i++) av[i] = Qs[ty * 4 + i][k];
            #pragma unroll
            for (int j = 0; j < 4; j++) bv[j] = Ks[tx * 4 + j][k];
            #pragma unroll
            for (int i = 0; i < 4; i++)
                #pragma unroll
                for (int j = 0; j < 4; j++)
                    acc[i][j] += av[i] * bv[j];
        }

        #pragma unroll
        for (int i = 0; i < 4; i++) {
            const int rr = ty * 4 + i;
            if (rr < nr) {
                float* arow = attn + ((size_t)h * NP + (r0 + rr)) * NL;
                #pragma unroll
                for (int j = 0; j < 4; j++) {
                    const int c = lc + tx * 4 + j;
                    if (c < l1) arow[c] = acc[i][j];
                }
            }
        }
        __syncthreads();
    }
}

// ---------------------------------------------------------------------------
// Softmax in-place over each row's in-batch range. Warp per (p, h).
// ---------------------------------------------------------------------------
__global__ void softmax_kernel(const int* __restrict__ bp, float* __restrict__ attn)
{
    const int g = blockIdx.x * 8 + (threadIdx.x >> 5);   // global (p,h) index
    const int lane = threadIdx.x & 31;
    const int p = g / NH;
    const int h = g % NH;

    const int b = bp[p];
    const int l0 = g_lstart[b], l1 = g_lend[b];
    if (l1 <= l0) return;

    float* row = attn + ((size_t)h * NP + p) * NL;

    float mx = -1e30f;
    for (int l = l0 + lane; l < l1; l += 32) mx = fmaxf(mx, row[l]);
    #pragma unroll
    for (int o = 16; o; o >>= 1) mx = fmaxf(mx, __shfl_xor_sync(0xffffffffu, mx, o));

    float sum = 0.f;
    for (int l = l0 + lane; l < l1; l += 32) sum += __expf(row[l] - mx);
    #pragma unroll
    for (int o = 16; o; o >>= 1) sum += __shfl_xor_sync(0xffffffffu, sum, o);
    const float inv = 1.f / sum;

    for (int l = l0 + lane; l < l1; l += 32) row[l] = __expf(row[l] - mx) * inv;
}

// ---------------------------------------------------------------------------
// Context: per (row-tile, head). C[p][d] = sum_l P[p][l] * V[l][d]
// Writes scrambled layout of transpose(0,1).view(-1,512): (h*NP+p)*64 + d.
// ---------------------------------------------------------------------------
__global__ void ctx_kernel(const float* __restrict__ attn,
                           const float* __restrict__ Vm,
                           float* __restrict__ ctx)
{
    const int b = g_tile_b[blockIdx.x];
    if (b < 0) return;
    const int r0 = g_tile_r[blockIdx.x];
    const int nr = min(64, g_pend[b] - r0);
    const int l0 = g_lstart[b], l1 = g_lend[b];
    const int h  = blockIdx.y;

    __shared__ float Ps[64][65];   // [row][l]
    __shared__ float Vs[64][65];   // [d][l]  (transposed V chunk)

    const int t  = threadIdx.x;
    const int tx = t & 15;
    const int ty = t >> 4;

    float acc[4][4] = {};

    for (int lc = l0; lc < l1; lc += 64) {
        for (int i = t; i < 64 * 64; i += 256) {
            const int row = i >> 6, li = i & 63;
            Ps[row][li] = (row < nr && lc + li < l1)
                        ? attn[((size_t)h * NP + (r0 + row)) * NL + lc + li] : 0.f;
        }
        for (int i = t; i < 64 * 64; i += 256) {
            const int l = i >> 6, d = i & 63;
            Vs[d][l] = (lc + l < l1) ? Vm[(size_t)(lc + l) * DM + h * 64 + d] : 0.f;
        }
        __syncthreads();

        #pragma unroll
        for (int k = 0; k < 64; k++) {
            float av[4], bv[4];
            #pragma unroll
            for (int i = 0; i < 4; i++) av[i] = Ps[ty * 4 + i][k];
            #pragma unroll
            for (int j = 0; j < 4; j++) bv[j] = Vs[tx * 4 + j][k];
            #pragma unroll
            for (int i = 0; i < 4; i++)
                #pragma unroll
                for (int j = 0; j < 4; j++)
                    acc[i][j] += av[i] * bv[j];
        }
        __syncthreads();
    }

    #pragma unroll
    for (int i = 0; i < 4; i++) {
        const int rr = ty * 4 + i;
        if (rr < nr) {
            #pragma unroll
            for (int j = 0; j < 4; j++)
                ctx[((size_t)h * NP + (r0 + rr)) * 64 + tx * 4 + j] = acc[i][j];
        }
    }
}

// ---------------------------------------------------------------------------
// LayerNorm: warp per row over 512 features.
// ---------------------------------------------------------------------------
__global__ void ln_kernel(const float* __restrict__ X,
                          const float* __restrict__ gamma,
                          const float* __restrict__ beta,
                          float* __restrict__ out)
{
    const int row  = blockIdx.x * 8 + (threadIdx.x >> 5);
    const int lane = threadIdx.x & 31;
    const float* xr = X + (size_t)row * DM;

    float v[16];
    float s = 0.f;
    #pragma unroll
    for (int i = 0; i < 16; i++) { v[i] = xr[lane + i * 32]; s += v[i]; }
    #pragma unroll
    for (int o = 16; o; o >>= 1) s += __shfl_xor_sync(0xffffffffu, s, o);
    const float mu = s * (1.f / 512.f);

    float q = 0.f;
    #pragma unroll
    for (int i = 0; i < 16; i++) { const float d = v[i] - mu; q += d * d; }
    #pragma unroll
    for (int o = 16; o; o >>= 1) q += __shfl_xor_sync(0xffffffffu, q, o);
    const float rstd = rsqrtf(q * (1.f / 512.f) + 1e-5f);

    #pragma unroll
    for (int i = 0; i < 16; i++) {
        const int c = lane + i * 32;
        out[(size_t)row * DM + c] = (v[i] - mu) * rstd * gamma[c] + beta[c];
    }
}

// ---------------------------------------------------------------------------
extern "C" void kernel_launch(void* const* d_in, const int* in_sizes, int n_in,
                              void* d_out, int out_size)
{
    const float* protein = (const float*)d_in[0];
    const float* ligand  = (const float*)d_in[1];
    const int* bp_raw    = (const int*)d_in[2];
    const int* bl_raw    = (const int*)d_in[3];
    const float* Wq = (const float*)d_in[4];
    const float* bq = (const float*)d_in[5];
    const float* Wk = (const float*)d_in[6];
    const float* bk = (const float*)d_in[7];
    const float* Wv = (const float*)d_in[8];
    const float* bv = (const float*)d_in[9];
    const float* Wo = (const float*)d_in[10];
    const float* bo = (const float*)d_in[11];
    const float* gamma = (const float*)d_in[12];
    const float* beta  = (const float*)d_in[13];

    float* out  = (float*)d_out;                      // [4096, 512]
    float* attn = out + (size_t)NP * DM;              // [1, 8, 4096, 2048]

    float *Qp, *Kp, *Vp, *Cp, *Tp;
    int *bpp, *blp;
    cudaGetSymbolAddress((void**)&Qp, g_Q);
    cudaGetSymbolAddress((void**)&Kp, g_K);
    cudaGetSymbolAddress((void**)&Vp, g_V);
    cudaGetSymbolAddress((void**)&Cp, g_ctx);
    cudaGetSymbolAddress((void**)&Tp, g_tmp);
    cudaGetSymbolAddress((void**)&bpp, g_bp);
    cudaGetSymbolAddress((void**)&blp, g_bl);

    // Batch arrays -> int32, ranges + tile worklist
    prep_batch<<<8, 256>>>(bp_raw, NP, bpp);
    prep_batch<<<8, 256>>>(bl_raw, NL, blp);
    prep_meta<<<1, 256>>>(bpp, blp);

    // Zero the attn output (covers all masked positions exactly)
    zero_attn<<<8192, 256>>>((float4*)attn, (int)(((size_t)NH * NP * NL) / 4));

    // Projections
    gemm_nt_bias<<<dim3(8, NP / 64), 256>>>(protein, Wq, bq, nullptr, Qp);
    gemm_nt_bias<<<dim3(8, NL / 64), 256>>>(ligand,  Wk, bk, nullptr, Kp);
    gemm_nt_bias<<<dim3(8, NL / 64), 256>>>(ligand,  Wv, bv, nullptr, Vp);

    // Attention: scores -> softmax (in gmem) -> context
    score_kernel<<<dim3(MAXT, NH), 256>>>(Qp, Kp, attn);
    softmax_kernel<<<NP * NH / 8, 256>>>(bpp, attn);
    ctx_kernel<<<dim3(MAXT, NH), 256>>>(attn, Vp, Cp);

    // Output projection + residual, then LayerNorm
    gemm_nt_bias<<<dim3(8, NP / 64), 256>>>(Cp, Wo, bo, protein, Tp);
    ln_kernel<<<NP / 8, 256>>>(Tp, gamma, beta, out);
}

// round 8
// speedup vs baseline: 8.6708x; 1.5657x over previous
#include <cuda_runtime.h>
#include <cuda_bf16.h>
#include <cstdint>

#define NP 4096
#define NL 2048
#define DM 512
#define NH 8
#define DK 64
#define NB 16
#define MAXT 80   // max row tiles: 4096/64 + 16

// Scratch (allocation-free rule: __device__ globals)
__device__ float g_Q[NP * DM];
__device__ float g_K[NL * DM];
__device__ float g_V[NL * DM];
__device__ float g_ctx[NP * DM];
__device__ float g_tmp[NP * DM];
__device__ int   g_bp[NP];
__device__ int   g_bl[NL];
__device__ int   g_pstart[NB], g_pend[NB];
__device__ int   g_lstart[NB], g_lend[NB];
__device__ int   g_tile_b[MAXT], g_tile_r[MAXT];

__device__ __forceinline__ float to_tf32(float x) {
    float y;
    asm("cvt.rna.tf32.f32 %0, %1;" : "=f"(y) : "f"(x));
    return y;
}

// ---------------------------------------------------------------------------
// prep kernels
// ---------------------------------------------------------------------------
__global__ void prep_batch(const int* __restrict__ raw, int n, int* __restrict__ out)
{
    __shared__ int is32;
    if (threadIdx.x == 0) is32 = (raw[n - 1] != 0) ? 1 : 0;
    __syncthreads();
    for (int i = blockIdx.x * blockDim.x + threadIdx.x; i < n; i += gridDim.x * blockDim.x)
        out[i] = is32 ? raw[i] : raw[2 * i];
}

__global__ void prep_meta(const int* __restrict__ bp, const int* __restrict__ bl)
{
    const int t = threadIdx.x;
    if (t < NB) { g_pstart[t] = 0; g_pend[t] = 0; g_lstart[t] = 0; g_lend[t] = 0; }
    __syncthreads();
    for (int i = t; i < NP; i += blockDim.x) {
        const int b = bp[i];
        if (i == 0 || bp[i - 1] != b) g_pstart[b] = i;
        if (i == NP - 1 || bp[i + 1] != b) g_pend[b] = i + 1;
    }
    for (int i = t; i < NL; i += blockDim.x) {
        const int b = bl[i];
        if (i == 0 || bl[i - 1] != b) g_lstart[b] = i;
        if (i == NL - 1 || bl[i + 1] != b) g_lend[b] = i + 1;
    }
    __syncthreads();
    if (t == 0) {
        int idx = 0;
        for (int b = 0; b < NB; b++)
            for (int r = g_pstart[b]; r < g_pend[b]; r += 64) {
                g_tile_b[idx] = b; g_tile_r[idx] = r; idx++;
            }
        for (; idx < MAXT; idx++) g_tile_b[idx] = -1;
    }
}

__global__ void zero_attn(float4* __restrict__ p, int n4)
{
    int i = blockIdx.x * blockDim.x + threadIdx.x;
    const int stride = gridDim.x * blockDim.x;
    const float4 z = make_float4(0.f, 0.f, 0.f, 0.f);
    for (; i < n4; i += stride) p[i] = z;
}

// ---------------------------------------------------------------------------
// tf32 mma.sync GEMM: Y[n][m] = sum_k X[n][k]*W[m][k] + bias[m] (+ res)
// CTA tile 128x128, K-chunk 32, 8 warps (2x4), warp tile 64x32.
// mma.sync.aligned.m16n8k8.row.col.f32.tf32.tf32.f32 (portable, sm_80+).
// smem stride 36 floats: conflict-free for the quad fragment pattern and
// 144B row pitch keeps float4 staging stores 16B-aligned.
// ---------------------------------------------------------------------------
#define GPAD 36

__global__ void __launch_bounds__(256) gemm_tf32(const float* __restrict__ X,
                                                 const float* __restrict__ W,
                                                 const float* __restrict__ bias,
                                                 const float* __restrict__ res,
                                                 float* __restrict__ Y)
{
    __shared__ float Xs[128 * GPAD];
    __shared__ float Ws[128 * GPAD];

    const int t = threadIdx.x;
    const int lane = t & 31, w = t >> 5;
    const int wm = w >> 2, wn = w & 3;           // 2 x 4 warp grid
    const int row0 = blockIdx.y * 128;
    const int col0 = blockIdx.x * 128;
    const int m0 = wm * 64, n0 = wn * 32;
    const int gid = lane >> 2, tid4 = lane & 3;  // quad layout

    float d[4][4][4] = {};

    for (int k0 = 0; k0 < DM; k0 += 32) {
        // Stage 128x32 of X and W into smem (tf32-rounded)
        #pragma unroll
        for (int i = t; i < 1024; i += 256) {
            const int r = i >> 3, q = i & 7;
            float4 v = *reinterpret_cast<const float4*>(X + (size_t)(row0 + r) * DM + k0 + q * 4);
            v.x = to_tf32(v.x); v.y = to_tf32(v.y); v.z = to_tf32(v.z); v.w = to_tf32(v.w);
            *reinterpret_cast<float4*>(&Xs[r * GPAD + q * 4]) = v;
            float4 u = *reinterpret_cast<const float4*>(W + (size_t)(col0 + r) * DM + k0 + q * 4);
            u.x = to_tf32(u.x); u.y = to_tf32(u.y); u.z = to_tf32(u.z); u.w = to_tf32(u.w);
            *reinterpret_cast<float4*>(&Ws[r * GPAD + q * 4]) = u;
        }
        __syncthreads();

        #pragma unroll
        for (int kk = 0; kk < 32; kk += 8) {
            uint32_t a[4][4], b[4][2];
            #pragma unroll
            for (int mt = 0; mt < 4; mt++) {
                const int rb = m0 + mt * 16 + gid;
                a[mt][0] = __float_as_uint(Xs[rb * GPAD + kk + tid4]);
                a[mt][1] = __float_as_uint(Xs[(rb + 8) * GPAD + kk + tid4]);
                a[mt][2] = __float_as_uint(Xs[rb * GPAD + kk + tid4 + 4]);
                a[mt][3] = __float_as_uint(Xs[(rb + 8) * GPAD + kk + tid4 + 4]);
            }
            #pragma unroll
            for (int nt = 0; nt < 4; nt++) {
                const int nb = n0 + nt * 8 + gid;
                b[nt][0] = __float_as_uint(Ws[nb * GPAD + kk + tid4]);
                b[nt][1] = __float_as_uint(Ws[nb * GPAD + kk + tid4 + 4]);
            }
            #pragma unroll
            for (int mt = 0; mt < 4; mt++)
                #pragma unroll
                for (int nt = 0; nt < 4; nt++)
                    asm volatile(
                        "mma.sync.aligned.m16n8k8.row.col.f32.tf32.tf32.f32 "
                        "{%0,%1,%2,%3}, {%4,%5,%6,%7}, {%8,%9}, {%0,%1,%2,%3};"
                        : "+f"(d[mt][nt][0]), "+f"(d[mt][nt][1]),
                          "+f"(d[mt][nt][2]), "+f"(d[mt][nt][3])
                        : "r"(a[mt][0]), "r"(a[mt][1]), "r"(a[mt][2]), "r"(a[mt][3]),
                          "r"(b[nt][0]), "r"(b[nt][1]));
        }
        __syncthreads();
    }

    // Epilogue: bias (+ residual), float2 stores.
    #pragma unroll
    for (int mt = 0; mt < 4; mt++) {
        #pragma unroll
        for (int nt = 0; nt < 4; nt++) {
            const int r1 = row0 + m0 + mt * 16 + gid;
            const int c  = col0 + n0 + nt * 8 + tid4 * 2;
            const float b0 = bias[c], b1 = bias[c + 1];
            float2 o0 = make_float2(d[mt][nt][0] + b0, d[mt][nt][1] + b1);
            float2 o1 = make_float2(d[mt][nt][2] + b0, d[mt][nt][3] + b1);
            if (res) {
                const float2 r0v = *reinterpret_cast<const float2*>(res + (size_t)r1 * DM + c);
                const float2 r1v = *reinterpret_cast<const float2*>(res + (size_t)(r1 + 8) * DM + c);
                o0.x += r0v.x; o0.y += r0v.y;
                o1.x += r1v.x; o1.y += r1v.y;
            }
            *reinterpret_cast<float2*>(Y + (size_t)r1 * DM + c) = o0;
            *reinterpret_cast<float2*>(Y + (size_t)(r1 + 8) * DM + c) = o1;
        }
    }
}

// ---------------------------------------------------------------------------
// Scores: per (row-tile, head). S[p][l] = 0.125 * Q[p,:] . K[l,:]
// ---------------------------------------------------------------------------
__global__ void score_kernel(const float* __restrict__ Q,
                             const float* __restrict__ Km,
                             float* __restrict__ attn)
{
    const int b = g_tile_b[blockIdx.x];
    if (b < 0) return;
    const int r0 = g_tile_r[blockIdx.x];
    const int nr = min(64, g_pend[b] - r0);
    const int l0 = g_lstart[b], l1 = g_lend[b];
    const int h  = blockIdx.y;

    __shared__ float Qs[64][65];   // [row][k] (pre-scaled)
    __shared__ float Ks[64][65];   // [col][k]

    const int t  = threadIdx.x;
    const int tx = t & 15;
    const int ty = t >> 4;

    for (int i = t; i < 64 * 64; i += 256) {
        const int row = i >> 6, d = i & 63;
        Qs[row][d] = (row < nr) ? Q[(size_t)(r0 + row) * DM + h * 64 + d] * 0.125f : 0.f;
    }

    for (int lc = l0; lc < l1; lc += 64) {
        for (int i = t; i < 64 * 64; i += 256) {
            const int col = i >> 6, d = i & 63;
            Ks[col][d] = (lc + col < l1) ? Km[(size_t)(lc + col) * DM + h * 64 + d] : 0.f;
        }
        __syncthreads();

        float acc[4][4] = {};
        #pragma unroll
        for (int k = 0; k < 64; k++) {
            float av[4], bv[4];
            #pragma unroll
            for (int i = 0; i < 4; i++) av[i] = Qs[ty * 4 + i][k];
            #pragma unroll
            for (int j = 0; j < 4; j++) bv[j] = Ks[tx * 4 + j][k];
            #pragma unroll
            for (int i = 0; i < 4; i++)
                #pragma unroll
                for (int j = 0; j < 4; j++)
                    acc[i][j] += av[i] * bv[j];
        }

        #pragma unroll
        for (int i = 0; i < 4; i++) {
            const int rr = ty * 4 + i;
            if (rr < nr) {
                float* arow = attn + ((size_t)h * NP + (r0 + rr)) * NL;
                #pragma unroll
                for (int j = 0; j < 4; j++) {
                    const int c = lc + tx * 4 + j;
                    if (c < l1) arow[c] = acc[i][j];
                }
            }
        }
        __syncthreads();
    }
}

// ---------------------------------------------------------------------------
// Softmax in-place over each row's in-batch range. Warp per (p, h).
// ---------------------------------------------------------------------------
__global__ void softmax_kernel(const int* __restrict__ bp, float* __restrict__ attn)
{
    const int g = blockIdx.x * 8 + (threadIdx.x >> 5);
    const int lane = threadIdx.x & 31;
    const int p = g / NH;
    const int h = g % NH;

    const int b = bp[p];
    const int l0 = g_lstart[b], l1 = g_lend[b];
    if (l1 <= l0) return;

    float* row = attn + ((size_t)h * NP + p) * NL;

    float mx = -1e30f;
    for (int l = l0 + lane; l < l1; l += 32) mx = fmaxf(mx, row[l]);
    #pragma unroll
    for (int o = 16; o; o >>= 1) mx = fmaxf(mx, __shfl_xor_sync(0xffffffffu, mx, o));

    float sum = 0.f;
    for (int l = l0 + lane; l < l1; l += 32) sum += __expf(row[l] - mx);
    #pragma unroll
    for (int o = 16; o; o >>= 1) sum += __shfl_xor_sync(0xffffffffu, sum, o);
    const float inv = 1.f / sum;

    for (int l = l0 + lane; l < l1; l += 32) row[l] = __expf(row[l] - mx) * inv;
}

// ---------------------------------------------------------------------------
// Context: per (row-tile, head). C[p][d] = sum_l P[p][l] * V[l][d]
// ---------------------------------------------------------------------------
__global__ void ctx_kernel(const float* __restrict__ attn,
                           const float* __restrict__ Vm,
                           float* __restrict__ ctx)
{
    const int b = g_tile_b[blockIdx.x];
    if (b < 0) return;
    const int r0 = g_tile_r[blockIdx.x];
    const int nr = min(64, g_pend[b] - r0);
    const int l0 = g_lstart[b], l1 = g_lend[b];
    const int h  = blockIdx.y;

    __shared__ float Ps[64][65];   // [row][l]
    __shared__ float Vs[64][65];   // [d][l]

    const int t  = threadIdx.x;
    const int tx = t & 15;
    const int ty = t >> 4;

    float acc[4][4] = {};

    for (int lc = l0; lc < l1; lc += 64) {
        for (int i = t; i < 64 * 64; i += 256) {
            const int row = i >> 6, li = i & 63;
            Ps[row][li] = (row < nr && lc + li < l1)
                        ? attn[((size_t)h * NP + (r0 + row)) * NL + lc + li] : 0.f;
        }
        for (int i = t; i < 64 * 64; i += 256) {
            const int l = i >> 6, d = i & 63;
            Vs[d][l] = (lc + l < l1) ? Vm[(size_t)(lc + l) * DM + h * 64 + d] : 0.f;
        }
        __syncthreads();

        #pragma unroll
        for (int k = 0; k < 64; k++) {
            float av[4], bv[4];
            #pragma unroll
            for (int i = 0; i < 4; i++) av[i] = Ps[ty * 4 + i][k];
            #pragma unroll
            for (int j = 0; j < 4; j++) bv[j] = Vs[tx * 4 + j][k];
            #pragma unroll
            for (int i = 0; i < 4; i++)
                #pragma unroll
                for (int j = 0; j < 4; j++)
                    acc[i][j] += av[i] * bv[j];
        }
        __syncthreads();
    }

    #pragma unroll
    for (int i = 0; i < 4; i++) {
        const int rr = ty * 4 + i;
        if (rr < nr) {
            #pragma unroll
            for (int j = 0; j < 4; j++)
                ctx[((size_t)h * NP + (r0 + rr)) * 64 + tx * 4 + j] = acc[i][j];
        }
    }
}

// ---------------------------------------------------------------------------
// LayerNorm: warp per row over 512 features.
// ---------------------------------------------------------------------------
__global__ void ln_kernel(const float* __restrict__ X,
                          const float* __restrict__ gamma,
                          const float* __restrict__ beta,
                          float* __restrict__ out)
{
    const int row  = blockIdx.x * 8 + (threadIdx.x >> 5);
    const int lane = threadIdx.x & 31;
    const float* xr = X + (size_t)row * DM;

    float v[16];
    float s = 0.f;
    #pragma unroll
    for (int i = 0; i < 16; i++) { v[i] = xr[lane + i * 32]; s += v[i]; }
    #pragma unroll
    for (int o = 16; o; o >>= 1) s += __shfl_xor_sync(0xffffffffu, s, o);
    const float mu = s * (1.f / 512.f);

    float q = 0.f;
    #pragma unroll
    for (int i = 0; i < 16; i++) { const float d = v[i] - mu; q += d * d; }
    #pragma unroll
    for (int o = 16; o; o >>= 1) q += __shfl_xor_sync(0xffffffffu, q, o);
    const float rstd = rsqrtf(q * (1.f / 512.f) + 1e-5f);

    #pragma unroll
    for (int i = 0; i < 16; i++) {
        const int c = lane + i * 32;
        out[(size_t)row * DM + c] = (v[i] - mu) * rstd * gamma[c] + beta[c];
    }
}

// ---------------------------------------------------------------------------
extern "C" void kernel_launch(void* const* d_in, const int* in_sizes, int n_in,
                              void* d_out, int out_size)
{
    const float* protein = (const float*)d_in[0];
    const float* ligand  = (const float*)d_in[1];
    const int* bp_raw    = (const int*)d_in[2];
    const int* bl_raw    = (const int*)d_in[3];
    const float* Wq = (const float*)d_in[4];
    const float* bq = (const float*)d_in[5];
    const float* Wk = (const float*)d_in[6];
    const float* bk = (const float*)d_in[7];
    const float* Wv = (const float*)d_in[8];
    const float* bv = (const float*)d_in[9];
    const float* Wo = (const float*)d_in[10];
    const float* bo = (const float*)d_in[11];
    const float* gamma = (const float*)d_in[12];
    const float* beta  = (const float*)d_in[13];

    float* out  = (float*)d_out;                      // [4096, 512]
    float* attn = out + (size_t)NP * DM;              // [1, 8, 4096, 2048]

    float *Qp, *Kp, *Vp, *Cp, *Tp;
    int *bpp, *blp;
    cudaGetSymbolAddress((void**)&Qp, g_Q);
    cudaGetSymbolAddress((void**)&Kp, g_K);
    cudaGetSymbolAddress((void**)&Vp, g_V);
    cudaGetSymbolAddress((void**)&Cp, g_ctx);
    cudaGetSymbolAddress((void**)&Tp, g_tmp);
    cudaGetSymbolAddress((void**)&bpp, g_bp);
    cudaGetSymbolAddress((void**)&blp, g_bl);

    // Batch arrays -> int32, ranges + tile worklist
    prep_batch<<<8, 256>>>(bp_raw, NP, bpp);
    prep_batch<<<8, 256>>>(bl_raw, NL, blp);
    prep_meta<<<1, 256>>>(bpp, blp);

    // Zero the attn output (covers all masked positions exactly)
    zero_attn<<<8192, 256>>>((float4*)attn, (int)(((size_t)NH * NP * NL) / 4));

    // Projections on tensor cores (tf32 mma.sync)
    gemm_tf32<<<dim3(DM / 128, NP / 128), 256>>>(protein, Wq, bq, nullptr, Qp);
    gemm_tf32<<<dim3(DM / 128, NL / 128), 256>>>(ligand,  Wk, bk, nullptr, Kp);
    gemm_tf32<<<dim3(DM / 128, NL / 128), 256>>>(ligand,  Wv, bv, nullptr, Vp);

    // Attention: scores -> softmax (in gmem) -> context
    score_kernel<<<dim3(MAXT, NH), 256>>>(Qp, Kp, attn);
    softmax_kernel<<<NP * NH / 8, 256>>>(bpp, attn);
    ctx_kernel<<<dim3(MAXT, NH), 256>>>(attn, Vp, Cp);

    // Output projection + residual, then LayerNorm
    gemm_tf32<<<dim3(DM / 128, NP / 128), 256>>>(Cp, Wo, bo, protein, Tp);
    ln_kernel<<<NP / 8, 256>>>(Tp, gamma, beta, out);
}

// round 9
// speedup vs baseline: 9.5139x; 1.0972x over previous
#include <cuda_runtime.h>
#include <cuda_bf16.h>
#include <cstdint>

#define NP 4096
#define NL 2048
#define DM 512
#define NH 8
#define DK 64
#define NB 16
#define MAXT 80   // max row tiles: 4096/64 + 16

// Scratch (allocation-free rule: __device__ globals)
__device__ float g_Q[NP * DM];
__device__ float g_K[NL * DM];
__device__ float g_V[NL * DM];
__device__ float g_ctx[NP * DM];
__device__ float g_tmp[NP * DM];
__device__ int   g_bp[NP];
__device__ int   g_bl[NL];
__device__ int   g_pstart[NB], g_pend[NB];
__device__ int   g_lstart[NB], g_lend[NB];
__device__ int   g_tile_b[MAXT], g_tile_r[MAXT];

__device__ __forceinline__ float to_tf32(float x) {
    float y;
    asm("cvt.rna.tf32.f32 %0, %1;" : "=f"(y) : "f"(x));
    return y;
}

#define MMA_TF32(d, a, b) \
    asm volatile("mma.sync.aligned.m16n8k8.row.col.f32.tf32.tf32.f32 " \
        "{%0,%1,%2,%3}, {%4,%5,%6,%7}, {%8,%9}, {%0,%1,%2,%3};" \
        : "+f"((d)[0]), "+f"((d)[1]), "+f"((d)[2]), "+f"((d)[3]) \
        : "r"((a)[0]), "r"((a)[1]), "r"((a)[2]), "r"((a)[3]), \
          "r"((b)[0]), "r"((b)[1]))

// ---------------------------------------------------------------------------
// One-shot prep: batch arrays -> int32 (robust to int32/int64 dtype),
// per-batch ranges, row-tile worklist. Single CTA.
// ---------------------------------------------------------------------------
__global__ void prep_all(const int* __restrict__ bpraw, const int* __restrict__ blraw)
{
    const int t = threadIdx.x;
    __shared__ int is32p, is32l;
    if (t == 0) { is32p = (bpraw[NP - 1] != 0); is32l = (blraw[NL - 1] != 0); }
    if (t < NB) { g_pstart[t] = 0; g_pend[t] = 0; g_lstart[t] = 0; g_lend[t] = 0; }
    __syncthreads();
    for (int i = t; i < NP; i += 256) g_bp[i] = is32p ? bpraw[i] : bpraw[2 * i];
    for (int i = t; i < NL; i += 256) g_bl[i] = is32l ? blraw[i] : blraw[2 * i];
    __syncthreads();
    for (int i = t; i < NP; i += 256) {
        const int b = g_bp[i];
        if (i == 0 || g_bp[i - 1] != b) g_pstart[b] = i;
        if (i == NP - 1 || g_bp[i + 1] != b) g_pend[b] = i + 1;
    }
    for (int i = t; i < NL; i += 256) {
        const int b = g_bl[i];
        if (i == 0 || g_bl[i - 1] != b) g_lstart[b] = i;
        if (i == NL - 1 || g_bl[i + 1] != b) g_lend[b] = i + 1;
    }
    __syncthreads();
    if (t == 0) {
        int idx = 0;
        for (int b = 0; b < NB; b++)
            for (int r = g_pstart[b]; r < g_pend[b]; r += 64) {
                g_tile_b[idx] = b; g_tile_r[idx] = r; idx++;
            }
        for (; idx < MAXT; idx++) g_tile_b[idx] = -1;
    }
}

// ---------------------------------------------------------------------------
// tf32 mma GEMM tile (device fn): Y[128,128] = X[128,K] W[128,K]^T + bias (+res)
// 8 warps (2x4), warp tile 64x32.
// ---------------------------------------------------------------------------
#define GPAD 36

__device__ __forceinline__ void gemm_tile(const float* __restrict__ X,
                                          const float* __restrict__ W,
                                          const float* __restrict__ bias,
                                          const float* __restrict__ res,
                                          float* __restrict__ Y,
                                          int row0, int col0)
{
    __shared__ float Xs[128 * GPAD];
    __shared__ float Ws[128 * GPAD];

    const int t = threadIdx.x;
    const int lane = t & 31, w = t >> 5;
    const int wm = w >> 2, wn = w & 3;
    const int m0 = wm * 64, n0 = wn * 32;
    const int gid = lane >> 2, q4 = lane & 3;

    float d[4][4][4] = {};

    for (int k0 = 0; k0 < DM; k0 += 32) {
        #pragma unroll
        for (int i = t; i < 1024; i += 256) {
            const int r = i >> 3, q = i & 7;
            float4 v = *reinterpret_cast<const float4*>(X + (size_t)(row0 + r) * DM + k0 + q * 4);
            v.x = to_tf32(v.x); v.y = to_tf32(v.y); v.z = to_tf32(v.z); v.w = to_tf32(v.w);
            *reinterpret_cast<float4*>(&Xs[r * GPAD + q * 4]) = v;
            float4 u = *reinterpret_cast<const float4*>(W + (size_t)(col0 + r) * DM + k0 + q * 4);
            u.x = to_tf32(u.x); u.y = to_tf32(u.y); u.z = to_tf32(u.z); u.w = to_tf32(u.w);
            *reinterpret_cast<float4*>(&Ws[r * GPAD + q * 4]) = u;
        }
        __syncthreads();

        #pragma unroll
        for (int kk = 0; kk < 32; kk += 8) {
            uint32_t a[4][4], b[4][2];
            #pragma unroll
            for (int mt = 0; mt < 4; mt++) {
                const int rb = m0 + mt * 16 + gid;
                a[mt][0] = __float_as_uint(Xs[rb * GPAD + kk + q4]);
                a[mt][1] = __float_as_uint(Xs[(rb + 8) * GPAD + kk + q4]);
                a[mt][2] = __float_as_uint(Xs[rb * GPAD + kk + q4 + 4]);
                a[mt][3] = __float_as_uint(Xs[(rb + 8) * GPAD + kk + q4 + 4]);
            }
            #pragma unroll
            for (int nt = 0; nt < 4; nt++) {
                const int nb = n0 + nt * 8 + gid;
                b[nt][0] = __float_as_uint(Ws[nb * GPAD + kk + q4]);
                b[nt][1] = __float_as_uint(Ws[nb * GPAD + kk + q4 + 4]);
            }
            #pragma unroll
            for (int mt = 0; mt < 4; mt++)
                #pragma unroll
                for (int nt = 0; nt < 4; nt++)
                    MMA_TF32(d[mt][nt], a[mt], b[nt]);
        }
        __syncthreads();
    }

    #pragma unroll
    for (int mt = 0; mt < 4; mt++) {
        #pragma unroll
        for (int nt = 0; nt < 4; nt++) {
            const int r1 = row0 + m0 + mt * 16 + gid;
            const int c  = col0 + n0 + nt * 8 + q4 * 2;
            const float b0 = bias[c], b1 = bias[c + 1];
            float2 o0 = make_float2(d[mt][nt][0] + b0, d[mt][nt][1] + b1);
            float2 o1 = make_float2(d[mt][nt][2] + b0, d[mt][nt][3] + b1);
            if (res) {
                const float2 r0v = *reinterpret_cast<const float2*>(res + (size_t)r1 * DM + c);
                const float2 r1v = *reinterpret_cast<const float2*>(res + (size_t)(r1 + 8) * DM + c);
                o0.x += r0v.x; o0.y += r0v.y;
                o1.x += r1v.x; o1.y += r1v.y;
            }
            *reinterpret_cast<float2*>(Y + (size_t)r1 * DM + c) = o0;
            *reinterpret_cast<float2*>(Y + (size_t)(r1 + 8) * DM + c) = o1;
        }
    }
}

// ---------------------------------------------------------------------------
// Phase 1 fused kernel: CTAs [0,256) run Q/K/V projections (tensor-bound),
// CTAs [256, 256+4096) zero-fill the attn output (DRAM-bound). Overlapping
// the two hides the projection time under the compulsory 268MB zero write.
// ---------------------------------------------------------------------------
__global__ void __launch_bounds__(256) p1_kernel(
    const float* __restrict__ protein, const float* __restrict__ ligand,
    const float* __restrict__ Wq, const float* __restrict__ bq,
    const float* __restrict__ Wk, const float* __restrict__ bk,
    const float* __restrict__ Wv, const float* __restrict__ bv,
    float* __restrict__ Qp, float* __restrict__ Kp, float* __restrict__ Vp,
    float4* __restrict__ attn4)
{
    const int bx = blockIdx.x;
    if (bx < 256) {
        const float *X, *W, *bias; float* Y; int lb;
        if (bx < 128)      { X = protein; W = Wq; bias = bq; Y = Qp; lb = bx; }
        else if (bx < 192) { X = ligand;  W = Wk; bias = bk; Y = Kp; lb = bx - 128; }
        else               { X = ligand;  W = Wv; bias = bv; Y = Vp; lb = bx - 192; }
        gemm_tile(X, W, bias, nullptr, Y, (lb >> 2) * 128, (lb & 3) * 128);
    } else {
        const int z = bx - 256;                 // 0..4095, 4096 float4 each
        const float4 zero4 = make_float4(0.f, 0.f, 0.f, 0.f);
        const int base = z * 4096 + threadIdx.x;
        #pragma unroll
        for (int i = 0; i < 16; i++) attn4[base + i * 256] = zero4;
    }
}

// Standalone GEMM wrapper (output projection).
__global__ void __launch_bounds__(256) gemm_tf32(const float* __restrict__ X,
                                                 const float* __restrict__ W,
                                                 const float* __restrict__ bias,
                                                 const float* __restrict__ res,
                                                 float* __restrict__ Y)
{
    gemm_tile(X, W, bias, res, Y, blockIdx.y * 128, blockIdx.x * 128);
}

// ---------------------------------------------------------------------------
// Scores via tf32 mma: per (row-tile 64, head). S = (Q*0.125) . K^T over the
// batch's key range, written dense into attn gmem. Warp tile 32x16.
// ---------------------------------------------------------------------------
#define SPAD 68

__global__ void __launch_bounds__(256) score_mma(const float* __restrict__ Q,
                                                 const float* __restrict__ Km,
                                                 float* __restrict__ attn)
{
    const int b = g_tile_b[blockIdx.x];
    if (b < 0) return;
    const int r0 = g_tile_r[blockIdx.x];
    const int nr = min(64, g_pend[b] - r0);
    const int l0 = g_lstart[b], l1 = g_lend[b];
    const int h  = blockIdx.y;

    __shared__ float Qs[64 * SPAD];   // [row][k], prescaled
    __shared__ float Ks[64 * SPAD];   // [key][k]

    const int t = threadIdx.x;
    const int lane = t & 31, w = t >> 5;
    const int wm = w >> 2, wn = w & 3;
    const int m0 = wm * 32, n0 = wn * 16;
    const int gid = lane >> 2, q4 = lane & 3;

    for (int i = t; i < 64 * 64; i += 256) {
        const int row = i >> 6, dd = i & 63;
        Qs[row * SPAD + dd] = (row < nr)
            ? to_tf32(Q[(size_t)(r0 + row) * DM + h * 64 + dd] * 0.125f) : 0.f;
    }

    for (int lc = l0; lc < l1; lc += 64) {
        for (int i = t; i < 64 * 64; i += 256) {
            const int col = i >> 6, dd = i & 63;
            Ks[col * SPAD + dd] = (lc + col < l1)
                ? to_tf32(Km[(size_t)(lc + col) * DM + h * 64 + dd]) : 0.f;
        }
        __syncthreads();

        float d[2][2][4] = {};
        #pragma unroll
        for (int kk = 0; kk < 64; kk += 8) {
            uint32_t a[2][4], bb[2][2];
            #pragma unroll
            for (int mt = 0; mt < 2; mt++) {
                const int rb = m0 + mt * 16 + gid;
                a[mt][0] = __float_as_uint(Qs[rb * SPAD + kk + q4]);
                a[mt][1] = __float_as_uint(Qs[(rb + 8) * SPAD + kk + q4]);
                a[mt][2] = __float_as_uint(Qs[rb * SPAD + kk + q4 + 4]);
                a[mt][3] = __float_as_uint(Qs[(rb + 8) * SPAD + kk + q4 + 4]);
            }
            #pragma unroll
            for (int nt = 0; nt < 2; nt++) {
                const int nb = n0 + nt * 8 + gid;
                bb[nt][0] = __float_as_uint(Ks[nb * SPAD + kk + q4]);
                bb[nt][1] = __float_as_uint(Ks[nb * SPAD + kk + q4 + 4]);
            }
            #pragma unroll
            for (int mt = 0; mt < 2; mt++)
                #pragma unroll
                for (int nt = 0; nt < 2; nt++)
                    MMA_TF32(d[mt][nt], a[mt], bb[nt]);
        }

        #pragma unroll
        for (int mt = 0; mt < 2; mt++) {
            #pragma unroll
            for (int nt = 0; nt < 2; nt++) {
                const int rr = m0 + mt * 16 + gid;
                const int c  = lc + n0 + nt * 8 + q4 * 2;
                float* a0 = attn + ((size_t)h * NP + (r0 + rr)) * NL;
                float* a1 = a0 + 8 * NL;
                if (rr < nr) {
                    if (c < l1)     a0[c]     = d[mt][nt][0];
                    if (c + 1 < l1) a0[c + 1] = d[mt][nt][1];
                }
                if (rr + 8 < nr) {
                    if (c < l1)     a1[c]     = d[mt][nt][2];
                    if (c + 1 < l1) a1[c + 1] = d[mt][nt][3];
                }
            }
        }
        __syncthreads();
    }
}

// ---------------------------------------------------------------------------
// Softmax in-place over each row's in-batch range. Warp per (p, h).
// ---------------------------------------------------------------------------
__global__ void softmax_kernel(float* __restrict__ attn)
{
    const int g = blockIdx.x * 8 + (threadIdx.x >> 5);
    const int lane = threadIdx.x & 31;
    const int p = g / NH;
    const int h = g % NH;

    const int b = g_bp[p];
    const int l0 = g_lstart[b], l1 = g_lend[b];
    if (l1 <= l0) return;

    float* row = attn + ((size_t)h * NP + p) * NL;

    float mx = -1e30f;
    for (int l = l0 + lane; l < l1; l += 32) mx = fmaxf(mx, row[l]);
    #pragma unroll
    for (int o = 16; o; o >>= 1) mx = fmaxf(mx, __shfl_xor_sync(0xffffffffu, mx, o));

    float sum = 0.f;
    for (int l = l0 + lane; l < l1; l += 32) sum += __expf(row[l] - mx);
    #pragma unroll
    for (int o = 16; o; o >>= 1) sum += __shfl_xor_sync(0xffffffffu, sum, o);
    const float inv = 1.f / sum;

    for (int l = l0 + lane; l < l1; l += 32) row[l] = __expf(row[l] - mx) * inv;
}

// ---------------------------------------------------------------------------
// Context via tf32 mma: per (row-tile 64, head). C = P . V over key range.
// Ps [row][l] PAD 68; Vs natural [l][d] PAD 72 (conflict-free staging +
// B-fragment loads). Writes scrambled layout (h*NP+p)*64 + d.
// ---------------------------------------------------------------------------
#define VPAD 72

__global__ void __launch_bounds__(256) ctx_mma(const float* __restrict__ attn,
                                               const float* __restrict__ Vm,
                                               float* __restrict__ ctx)
{
    const int b = g_tile_b[blockIdx.x];
    if (b < 0) return;
    const int r0 = g_tile_r[blockIdx.x];
    const int nr = min(64, g_pend[b] - r0);
    const int l0 = g_lstart[b], l1 = g_lend[b];
    const int h  = blockIdx.y;

    __shared__ float Ps[64 * SPAD];   // [row][l]
    __shared__ float Vs[64 * VPAD];   // [l][d]

    const int t = threadIdx.x;
    const int lane = t & 31, w = t >> 5;
    const int wm = w >> 2, wn = w & 3;
    const int m0 = wm * 32, n0 = wn * 16;
    const int gid = lane >> 2, q4 = lane & 3;

    float d[2][2][4] = {};

    for (int lc = l0; lc < l1; lc += 64) {
        for (int i = t; i < 64 * 64; i += 256) {
            const int row = i >> 6, li = i & 63;
            Ps[row * SPAD + li] = (row < nr && lc + li < l1)
                ? to_tf32(attn[((size_t)h * NP + (r0 + row)) * NL + lc + li]) : 0.f;
        }
        for (int i = t; i < 64 * 64; i += 256) {
            const int l = i >> 6, dd = i & 63;
            Vs[l * VPAD + dd] = (lc + l < l1)
                ? to_tf32(Vm[(size_t)(lc + l) * DM + h * 64 + dd]) : 0.f;
        }
        __syncthreads();

        #pragma unroll
        for (int kk = 0; kk < 64; kk += 8) {
            uint32_t a[2][4], bb[2][2];
            #pragma unroll
            for (int mt = 0; mt < 2; mt++) {
                const int rb = m0 + mt * 16 + gid;
                a[mt][0] = __float_as_uint(Ps[rb * SPAD + kk + q4]);
                a[mt][1] = __float_as_uint(Ps[(rb + 8) * SPAD + kk + q4]);
                a[mt][2] = __float_as_uint(Ps[rb * SPAD + kk + q4 + 4]);
                a[mt][3] = __float_as_uint(Ps[(rb + 8) * SPAD + kk + q4 + 4]);
            }
            #pragma unroll
            for (int nt = 0; nt < 2; nt++) {
                const int nb = n0 + nt * 8 + gid;   // d-column
                bb[nt][0] = __float_as_uint(Vs[(kk + q4) * VPAD + nb]);
                bb[nt][1] = __float_as_uint(Vs[(kk + q4 + 4) * VPAD + nb]);
            }
            #pragma unroll
            for (int mt = 0; mt < 2; mt++)
                #pragma unroll
                for (int nt = 0; nt < 2; nt++)
                    MMA_TF32(d[mt][nt], a[mt], bb[nt]);
        }
        __syncthreads();
    }

    #pragma unroll
    for (int mt = 0; mt < 2; mt++) {
        #pragma unroll
        for (int nt = 0; nt < 2; nt++) {
            const int rr = m0 + mt * 16 + gid;
            const int c  = n0 + nt * 8 + q4 * 2;
            if (rr < nr) {
                float* o = ctx + ((size_t)h * NP + (r0 + rr)) * 64;
                o[c] = d[mt][nt][0]; o[c + 1] = d[mt][nt][1];
            }
            if (rr + 8 < nr) {
                float* o = ctx + ((size_t)h * NP + (r0 + rr + 8)) * 64;
                o[c] = d[mt][nt][2]; o[c + 1] = d[mt][nt][3];
            }
        }
    }
}

// ---------------------------------------------------------------------------
// LayerNorm: warp per row over 512 features.
// ---------------------------------------------------------------------------
__global__ void ln_kernel(const float* __restrict__ X,
                          const float* __restrict__ gamma,
                          const float* __restrict__ beta,
                          float* __restrict__ out)
{
    const int row  = blockIdx.x * 8 + (threadIdx.x >> 5);
    const int lane = threadIdx.x & 31;
    const float* xr = X + (size_t)row * DM;

    float v[16];
    float s = 0.f;
    #pragma unroll
    for (int i = 0; i < 16; i++) { v[i] = xr[lane + i * 32]; s += v[i]; }
    #pragma unroll
    for (int o = 16; o; o >>= 1) s += __shfl_xor_sync(0xffffffffu, s, o);
    const float mu = s * (1.f / 512.f);

    float q = 0.f;
    #pragma unroll
    for (int i = 0; i < 16; i++) { const float d = v[i] - mu; q += d * d; }
    #pragma unroll
    for (int o = 16; o; o >>= 1) q += __shfl_xor_sync(0xffffffffu, q, o);
    const float rstd = rsqrtf(q * (1.f / 512.f) + 1e-5f);

    #pragma unroll
    for (int i = 0; i < 16; i++) {
        const int c = lane + i * 32;
        out[(size_t)row * DM + c] = (v[i] - mu) * rstd * gamma[c] + beta[c];
    }
}

// ---------------------------------------------------------------------------
extern "C" void kernel_launch(void* const* d_in, const int* in_sizes, int n_in,
                              void* d_out, int out_size)
{
    const float* protein = (const float*)d_in[0];
    const float* ligand  = (const float*)d_in[1];
    const int* bp_raw    = (const int*)d_in[2];
    const int* bl_raw    = (const int*)d_in[3];
    const float* Wq = (const float*)d_in[4];
    const float* bq = (const float*)d_in[5];
    const float* Wk = (const float*)d_in[6];
    const float* bk = (const float*)d_in[7];
    const float* Wv = (const float*)d_in[8];
    const float* bv = (const float*)d_in[9];
    const float* Wo = (const float*)d_in[10];
    const float* bo = (const float*)d_in[11];
    const float* gamma = (const float*)d_in[12];
    const float* beta  = (const float*)d_in[13];

    float* out  = (float*)d_out;                      // [4096, 512]
    float* attn = out + (size_t)NP * DM;              // [1, 8, 4096, 2048]

    float *Qp, *Kp, *Vp, *Cp, *Tp;
    cudaGetSymbolAddress((void**)&Qp, g_Q);
    cudaGetSymbolAddress((void**)&Kp, g_K);
    cudaGetSymbolAddress((void**)&Vp, g_V);
    cudaGetSymbolAddress((void**)&Cp, g_ctx);
    cudaGetSymbolAddress((void**)&Tp, g_tmp);

    // Prep (single CTA): batch dtype normalize + ranges + tile worklist
    prep_all<<<1, 256>>>(bp_raw, bl_raw);

    // Phase 1: Q/K/V projections overlapped with the attn zero-fill
    p1_kernel<<<256 + 4096, 256>>>(protein, ligand, Wq, bq, Wk, bk, Wv, bv,
                                   Qp, Kp, Vp, (float4*)attn);

    // Attention: scores -> softmax (in gmem) -> context, all on tensor cores
    score_mma<<<dim3(MAXT, NH), 256>>>(Qp, Kp, attn);
    softmax_kernel<<<NP * NH / 8, 256>>>(attn);
    ctx_mma<<<dim3(MAXT, NH), 256>>>(attn, Vp, Cp);

    // Output projection + residual, then LayerNorm
    gemm_tf32<<<dim3(DM / 128, NP / 128), 256>>>(Cp, Wo, bo, protein, Tp);
    ln_kernel<<<NP / 8, 256>>>(Tp, gamma, beta, out);
}

// round 11
// speedup vs baseline: 10.5481x; 1.1087x over previous
#include <cuda_runtime.h>
#include <cuda_bf16.h>
#include <cstdint>

#define NP 4096
#define NL 2048
#define DM 512
#define NH 8
#define DK 64
#define NB 16
#define MAXT 80   // max row tiles: 4096/64 + 16

// Scratch (allocation-free rule: __device__ globals)
__device__ float g_Q[NP * DM];
__device__ float g_K[NL * DM];
__device__ float g_V[NL * DM];
__device__ float g_ctx[NP * DM];
__device__ float g_tmp[NP * DM];
__device__ int   g_bp[NP];
__device__ int   g_bl[NL];
__device__ int   g_pstart[NB], g_pend[NB];
__device__ int   g_lstart[NB], g_lend[NB];
__device__ int   g_tile_b[MAXT], g_tile_r[MAXT];

__device__ __forceinline__ float to_tf32(float x) {
    float y;
    asm("cvt.rna.tf32.f32 %0, %1;" : "=f"(y) : "f"(x));
    return y;
}

#define MMA_TF32(d, a, b) \
    asm volatile("mma.sync.aligned.m16n8k8.row.col.f32.tf32.tf32.f32 " \
        "{%0,%1,%2,%3}, {%4,%5,%6,%7}, {%8,%9}, {%0,%1,%2,%3};" \
        : "+f"((d)[0]), "+f"((d)[1]), "+f"((d)[2]), "+f"((d)[3]) \
        : "r"((a)[0]), "r"((a)[1]), "r"((a)[2]), "r"((a)[3]), \
          "r"((b)[0]), "r"((b)[1]))

// ---------------------------------------------------------------------------
// tf32 mma GEMM tile (device fn): Y[128,128] = X[128,K] W[128,K]^T + bias (+res)
// 8 warps (2x4), warp tile 64x32.
// ---------------------------------------------------------------------------
#define GPAD 36

__device__ __forceinline__ void gemm_tile(const float* __restrict__ X,
                                          const float* __restrict__ W,
                                          const float* __restrict__ bias,
                                          const float* __restrict__ res,
                                          float* __restrict__ Y,
                                          int row0, int col0)
{
    __shared__ __align__(16) float Xs[128 * GPAD];
    __shared__ __align__(16) float Ws[128 * GPAD];

    const int t = threadIdx.x;
    const int lane = t & 31, w = t >> 5;
    const int wm = w >> 2, wn = w & 3;
    const int m0 = wm * 64, n0 = wn * 32;
    const int gid = lane >> 2, q4 = lane & 3;

    float d[4][4][4] = {};

    for (int k0 = 0; k0 < DM; k0 += 32) {
        #pragma unroll
        for (int i = t; i < 1024; i += 256) {
            const int r = i >> 3, q = i & 7;
            float4 v = *reinterpret_cast<const float4*>(X + (size_t)(row0 + r) * DM + k0 + q * 4);
            v.x = to_tf32(v.x); v.y = to_tf32(v.y); v.z = to_tf32(v.z); v.w = to_tf32(v.w);
            *reinterpret_cast<float4*>(&Xs[r * GPAD + q * 4]) = v;
            float4 u = *reinterpret_cast<const float4*>(W + (size_t)(col0 + r) * DM + k0 + q * 4);
            u.x = to_tf32(u.x); u.y = to_tf32(u.y); u.z = to_tf32(u.z); u.w = to_tf32(u.w);
            *reinterpret_cast<float4*>(&Ws[r * GPAD + q * 4]) = u;
        }
        __syncthreads();

        #pragma unroll
        for (int kk = 0; kk < 32; kk += 8) {
            uint32_t a[4][4], b[4][2];
            #pragma unroll
            for (int mt = 0; mt < 4; mt++) {
                const int rb = m0 + mt * 16 + gid;
                a[mt][0] = __float_as_uint(Xs[rb * GPAD + kk + q4]);
                a[mt][1] = __float_as_uint(Xs[(rb + 8) * GPAD + kk + q4]);
                a[mt][2] = __float_as_uint(Xs[rb * GPAD + kk + q4 + 4]);
                a[mt][3] = __float_as_uint(Xs[(rb + 8) * GPAD + kk + q4 + 4]);
            }
            #pragma unroll
            for (int nt = 0; nt < 4; nt++) {
                const int nb = n0 + nt * 8 + gid;
                b[nt][0] = __float_as_uint(Ws[nb * GPAD + kk + q4]);
                b[nt][1] = __float_as_uint(Ws[nb * GPAD + kk + q4 + 4]);
            }
            #pragma unroll
            for (int mt = 0; mt < 4; mt++)
                #pragma unroll
                for (int nt = 0; nt < 4; nt++)
                    MMA_TF32(d[mt][nt], a[mt], b[nt]);
        }
        __syncthreads();
    }

    #pragma unroll
    for (int mt = 0; mt < 4; mt++) {
        #pragma unroll
        for (int nt = 0; nt < 4; nt++) {
            const int r1 = row0 + m0 + mt * 16 + gid;
            const int c  = col0 + n0 + nt * 8 + q4 * 2;
            const float b0 = bias[c], b1 = bias[c + 1];
            float2 o0 = make_float2(d[mt][nt][0] + b0, d[mt][nt][1] + b1);
            float2 o1 = make_float2(d[mt][nt][2] + b0, d[mt][nt][3] + b1);
            if (res) {
                const float2 r0v = *reinterpret_cast<const float2*>(res + (size_t)r1 * DM + c);
                const float2 r1v = *reinterpret_cast<const float2*>(res + (size_t)(r1 + 8) * DM + c);
                o0.x += r0v.x; o0.y += r0v.y;
                o1.x += r1v.x; o1.y += r1v.y;
            }
            *reinterpret_cast<float2*>(Y + (size_t)r1 * DM + c) = o0;
            *reinterpret_cast<float2*>(Y + (size_t)(r1 + 8) * DM + c) = o1;
        }
    }
}

// ---------------------------------------------------------------------------
// Phase 1 fused kernel:
//   CTAs [0,256)        : Q/K/V projections (tensor-bound)
//   CTAs [256, 256+4096): zero-fill of attn output (DRAM-bound)
//   CTA  4352           : batch prep (dtype normalize, ranges, tile worklist)
// No shared scalars in the prep branch — keeps gemm_tile's smem 16B-aligned.
// ---------------------------------------------------------------------------
__global__ void __launch_bounds__(256) p1_kernel(
    const float* __restrict__ protein, const float* __restrict__ ligand,
    const int* __restrict__ bpraw, const int* __restrict__ blraw,
    const float* __restrict__ Wq, const float* __restrict__ bq,
    const float* __restrict__ Wk, const float* __restrict__ bk,
    const float* __restrict__ Wv, const float* __restrict__ bv,
    float* __restrict__ Qp, float* __restrict__ Kp, float* __restrict__ Vp,
    float4* __restrict__ attn4)
{
    const int bx = blockIdx.x;
    const int t = threadIdx.x;
    if (bx < 256) {
        const float *X, *W, *bias; float* Y; int lb;
        if (bx < 128)      { X = protein; W = Wq; bias = bq; Y = Qp; lb = bx; }
        else if (bx < 192) { X = ligand;  W = Wk; bias = bk; Y = Kp; lb = bx - 128; }
        else               { X = ligand;  W = Wv; bias = bv; Y = Vp; lb = bx - 192; }
        gemm_tile(X, W, bias, nullptr, Y, (lb >> 2) * 128, (lb & 3) * 128);
    } else if (bx < 256 + 4096) {
        const int z = bx - 256;                 // 0..4095, 4096 float4 each
        const float4 zero4 = make_float4(0.f, 0.f, 0.f, 0.f);
        const int base = z * 4096 + t;
        #pragma unroll
        for (int i = 0; i < 16; i++) attn4[base + i * 256] = zero4;
    } else {
        // prep: batch arrays -> int32, ranges, tile worklist.
        // Per-thread dtype detection (broadcast loads) — no shared scalars.
        const int is32p = (bpraw[NP - 1] != 0);
        const int is32l = (blraw[NL - 1] != 0);
        if (t < NB) { g_pstart[t] = 0; g_pend[t] = 0; g_lstart[t] = 0; g_lend[t] = 0; }
        for (int i = t; i < NP; i += 256) g_bp[i] = is32p ? bpraw[i] : bpraw[2 * i];
        for (int i = t; i < NL; i += 256) g_bl[i] = is32l ? blraw[i] : blraw[2 * i];
        __syncthreads();
        for (int i = t; i < NP; i += 256) {
            const int b = g_bp[i];
            if (i == 0 || g_bp[i - 1] != b) g_pstart[b] = i;
            if (i == NP - 1 || g_bp[i + 1] != b) g_pend[b] = i + 1;
        }
        for (int i = t; i < NL; i += 256) {
            const int b = g_bl[i];
            if (i == 0 || g_bl[i - 1] != b) g_lstart[b] = i;
            if (i == NL - 1 || g_bl[i + 1] != b) g_lend[b] = i + 1;
        }
        __syncthreads();
        if (t == 0) {
            int idx = 0;
            for (int b = 0; b < NB; b++)
                for (int r = g_pstart[b]; r < g_pend[b]; r += 64) {
                    g_tile_b[idx] = b; g_tile_r[idx] = r; idx++;
                }
            for (; idx < MAXT; idx++) g_tile_b[idx] = -1;
        }
    }
}

// Standalone GEMM wrapper (output projection).
__global__ void __launch_bounds__(256) gemm_tf32(const float* __restrict__ X,
                                                 const float* __restrict__ W,
                                                 const float* __restrict__ bias,
                                                 const float* __restrict__ res,
                                                 float* __restrict__ Y)
{
    gemm_tile(X, W, bias, res, Y, blockIdx.y * 128, blockIdx.x * 128);
}

// ---------------------------------------------------------------------------
// Scores + softmax fused: per (row-tile 64, head).
// Pass A: S = (Q*0.125) . K^T via tf32 mma, raw scores -> attn gmem (L2 hot).
// Pass B (in-kernel): warp-per-8-rows max -> exp(store) -> scale. Single exp.
// ---------------------------------------------------------------------------
#define SPAD 68

__global__ void __launch_bounds__(256) score_sm(const float* __restrict__ Q,
                                                const float* __restrict__ Km,
                                                float* __restrict__ attn)
{
    const int b = g_tile_b[blockIdx.x];
    if (b < 0) return;
    const int r0 = g_tile_r[blockIdx.x];
    const int nr = min(64, g_pend[b] - r0);
    const int l0 = g_lstart[b], l1 = g_lend[b];
    const int h  = blockIdx.y;

    __shared__ __align__(16) float Qs[64 * SPAD];   // [row][k], prescaled
    __shared__ __align__(16) float Ks[64 * SPAD];   // [key][k]

    const int t = threadIdx.x;
    const int lane = t & 31, w = t >> 5;
    const int wm = w >> 2, wn = w & 3;
    const int m0 = wm * 32, n0 = wn * 16;
    const int gid = lane >> 2, q4 = lane & 3;

    // Vectorized Q staging: 64 rows x 16 float4
    #pragma unroll
    for (int i = t; i < 1024; i += 256) {
        const int row = i >> 4, q = (i & 15) * 4;
        float4 v = make_float4(0.f, 0.f, 0.f, 0.f);
        if (row < nr)
            v = *reinterpret_cast<const float4*>(Q + (size_t)(r0 + row) * DM + h * 64 + q);
        v.x = to_tf32(v.x * 0.125f); v.y = to_tf32(v.y * 0.125f);
        v.z = to_tf32(v.z * 0.125f); v.w = to_tf32(v.w * 0.125f);
        *reinterpret_cast<float4*>(&Qs[row * SPAD + q]) = v;
    }

    for (int lc = l0; lc < l1; lc += 64) {
        #pragma unroll
        for (int i = t; i < 1024; i += 256) {
            const int col = i >> 4, q = (i & 15) * 4;
            float4 v = make_float4(0.f, 0.f, 0.f, 0.f);
            if (lc + col < l1)
                v = *reinterpret_cast<const float4*>(Km + (size_t)(lc + col) * DM + h * 64 + q);
            v.x = to_tf32(v.x); v.y = to_tf32(v.y); v.z = to_tf32(v.z); v.w = to_tf32(v.w);
            *reinterpret_cast<float4*>(&Ks[col * SPAD + q]) = v;
        }
        __syncthreads();

        float d[2][2][4] = {};
        #pragma unroll
        for (int kk = 0; kk < 64; kk += 8) {
            uint32_t a[2][4], bb[2][2];
            #pragma unroll
            for (int mt = 0; mt < 2; mt++) {
                const int rb = m0 + mt * 16 + gid;
                a[mt][0] = __float_as_uint(Qs[rb * SPAD + kk + q4]);
                a[mt][1] = __float_as_uint(Qs[(rb + 8) * SPAD + kk + q4]);
                a[mt][2] = __float_as_uint(Qs[rb * SPAD + kk + q4 + 4]);
                a[mt][3] = __float_as_uint(Qs[(rb + 8) * SPAD + kk + q4 + 4]);
            }
            #pragma unroll
            for (int nt = 0; nt < 2; nt++) {
                const int nb = n0 + nt * 8 + gid;
                bb[nt][0] = __float_as_uint(Ks[nb * SPAD + kk + q4]);
                bb[nt][1] = __float_as_uint(Ks[nb * SPAD + kk + q4 + 4]);
            }
            #pragma unroll
            for (int mt = 0; mt < 2; mt++)
                #pragma unroll
                for (int nt = 0; nt < 2; nt++)
                    MMA_TF32(d[mt][nt], a[mt], bb[nt]);
        }

        #pragma unroll
        for (int mt = 0; mt < 2; mt++) {
            #pragma unroll
            for (int nt = 0; nt < 2; nt++) {
                const int rr = m0 + mt * 16 + gid;
                const int c  = lc + n0 + nt * 8 + q4 * 2;
                float* a0 = attn + ((size_t)h * NP + (r0 + rr)) * NL;
                float* a1 = a0 + 8 * NL;
                if (rr < nr) {
                    if (c < l1)     a0[c]     = d[mt][nt][0];
                    if (c + 1 < l1) a0[c + 1] = d[mt][nt][1];
                }
                if (rr + 8 < nr) {
                    if (c < l1)     a1[c]     = d[mt][nt][2];
                    if (c + 1 < l1) a1[c + 1] = d[mt][nt][3];
                }
            }
        }
        __syncthreads();
    }

    // Pass B: softmax over [l0, l1) per row; raw scores are L2-hot.
    #pragma unroll
    for (int rr8 = 0; rr8 < 8; rr8++) {
        const int row = w * 8 + rr8;
        if (row >= nr) continue;
        float* arow = attn + ((size_t)h * NP + (r0 + row)) * NL;

        float mx = -1e30f;
        for (int l = l0 + lane; l < l1; l += 32) mx = fmaxf(mx, arow[l]);
        #pragma unroll
        for (int o = 16; o; o >>= 1) mx = fmaxf(mx, __shfl_xor_sync(0xffffffffu, mx, o));

        float sum = 0.f;
        for (int l = l0 + lane; l < l1; l += 32) {
            const float e = __expf(arow[l] - mx);
            arow[l] = e;
            sum += e;
        }
        #pragma unroll
        for (int o = 16; o; o >>= 1) sum += __shfl_xor_sync(0xffffffffu, sum, o);
        const float inv = 1.f / sum;

        for (int l = l0 + lane; l < l1; l += 32) arow[l] *= inv;
    }
}

// ---------------------------------------------------------------------------
// Context via tf32 mma: per (row-tile 64, head). C = P . V over key range.
// Writes scrambled layout (h*NP+p)*64 + d.
// ---------------------------------------------------------------------------
#define VPAD 72

__global__ void __launch_bounds__(256) ctx_mma(const float* __restrict__ attn,
                                               const float* __restrict__ Vm,
                                               float* __restrict__ ctx)
{
    const int b = g_tile_b[blockIdx.x];
    if (b < 0) return;
    const int r0 = g_tile_r[blockIdx.x];
    const int nr = min(64, g_pend[b] - r0);
    const int l0 = g_lstart[b], l1 = g_lend[b];
    const int h  = blockIdx.y;

    __shared__ __align__(16) float Ps[64 * SPAD];   // [row][l]
    __shared__ __align__(16) float Vs[64 * VPAD];   // [l][d]

    const int t = threadIdx.x;
    const int lane = t & 31, w = t >> 5;
    const int wm = w >> 2, wn = w & 3;
    const int m0 = wm * 32, n0 = wn * 16;
    const int gid = lane >> 2, q4 = lane & 3;

    float d[2][2][4] = {};

    for (int lc = l0; lc < l1; lc += 64) {
        // Ps staging scalar (lc alignment unknown)
        for (int i = t; i < 64 * 64; i += 256) {
            const int row = i >> 6, li = i & 63;
            Ps[row * SPAD + li] = (row < nr && lc + li < l1)
                ? to_tf32(attn[((size_t)h * NP + (r0 + row)) * NL + lc + li]) : 0.f;
        }
        // Vs staging vectorized
        #pragma unroll
        for (int i = t; i < 1024; i += 256) {
            const int l = i >> 4, q = (i & 15) * 4;
            float4 v = make_float4(0.f, 0.f, 0.f, 0.f);
            if (lc + l < l1)
                v = *reinterpret_cast<const float4*>(Vm + (size_t)(lc + l) * DM + h * 64 + q);
            v.x = to_tf32(v.x); v.y = to_tf32(v.y); v.z = to_tf32(v.z); v.w = to_tf32(v.w);
            *reinterpret_cast<float4*>(&Vs[l * VPAD + q]) = v;
        }
        __syncthreads();

        #pragma unroll
        for (int kk = 0; kk < 64; kk += 8) {
            uint32_t a[2][4], bb[2][2];
            #pragma unroll
            for (int mt = 0; mt < 2; mt++) {
                const int rb = m0 + mt * 16 + gid;
                a[mt][0] = __float_as_uint(Ps[rb * SPAD + kk + q4]);
                a[mt][1] = __float_as_uint(Ps[(rb + 8) * SPAD + kk + q4]);
                a[mt][2] = __float_as_uint(Ps[rb * SPAD + kk + q4 + 4]);
                a[mt][3] = __float_as_uint(Ps[(rb + 8) * SPAD + kk + q4 + 4]);
            }
            #pragma unroll
            for (int nt = 0; nt < 2; nt++) {
                const int nb = n0 + nt * 8 + gid;   // d-column
                bb[nt][0] = __float_as_uint(Vs[(kk + q4) * VPAD + nb]);
                bb[nt][1] = __float_as_uint(Vs[(kk + q4 + 4) * VPAD + nb]);
            }
            #pragma unroll
            for (int mt = 0; mt < 2; mt++)
                #pragma unroll
                for (int nt = 0; nt < 2; nt++)
                    MMA_TF32(d[mt][nt], a[mt], bb[nt]);
        }
        __syncthreads();
    }

    #pragma unroll
    for (int mt = 0; mt < 2; mt++) {
        #pragma unroll
        for (int nt = 0; nt < 2; nt++) {
            const int rr = m0 + mt * 16 + gid;
            const int c  = n0 + nt * 8 + q4 * 2;
            if (rr < nr) {
                float* o = ctx + ((size_t)h * NP + (r0 + rr)) * 64;
                o[c] = d[mt][nt][0]; o[c + 1] = d[mt][nt][1];
            }
            if (rr + 8 < nr) {
                float* o = ctx + ((size_t)h * NP + (r0 + rr + 8)) * 64;
                o[c] = d[mt][nt][2]; o[c + 1] = d[mt][nt][3];
            }
        }
    }
}

// ---------------------------------------------------------------------------
// LayerNorm: warp per row over 512 features.
// ---------------------------------------------------------------------------
__global__ void ln_kernel(const float* __restrict__ X,
                          const float* __restrict__ gamma,
                          const float* __restrict__ beta,
                          float* __restrict__ out)
{
    const int row  = blockIdx.x * 8 + (threadIdx.x >> 5);
    const int lane = threadIdx.x & 31;
    const float* xr = X + (size_t)row * DM;

    float v[16];
    float s = 0.f;
    #pragma unroll
    for (int i = 0; i < 16; i++) { v[i] = xr[lane + i * 32]; s += v[i]; }
    #pragma unroll
    for (int o = 16; o; o >>= 1) s += __shfl_xor_sync(0xffffffffu, s, o);
    const float mu = s * (1.f / 512.f);

    float q = 0.f;
    #pragma unroll
    for (int i = 0; i < 16; i++) { const float d = v[i] - mu; q += d * d; }
    #pragma unroll
    for (int o = 16; o; o >>= 1) q += __shfl_xor_sync(0xffffffffu, q, o);
    const float rstd = rsqrtf(q * (1.f / 512.f) + 1e-5f);

    #pragma unroll
    for (int i = 0; i < 16; i++) {
        const int c = lane + i * 32;
        out[(size_t)row * DM + c] = (v[i] - mu) * rstd * gamma[c] + beta[c];
    }
}

// ---------------------------------------------------------------------------
extern "C" void kernel_launch(void* const* d_in, const int* in_sizes, int n_in,
                              void* d_out, int out_size)
{
    const float* protein = (const float*)d_in[0];
    const float* ligand  = (const float*)d_in[1];
    const int* bp_raw    = (const int*)d_in[2];
    const int* bl_raw    = (const int*)d_in[3];
    const float* Wq = (const float*)d_in[4];
    const float* bq = (const float*)d_in[5];
    const float* Wk = (const float*)d_in[6];
    const float* bk = (const float*)d_in[7];
    const float* Wv = (const float*)d_in[8];
    const float* bv = (const float*)d_in[9];
    const float* Wo = (const float*)d_in[10];
    const float* bo = (const float*)d_in[11];
    const float* gamma = (const float*)d_in[12];
    const float* beta  = (const float*)d_in[13];

    float* out  = (float*)d_out;                      // [4096, 512]
    float* attn = out + (size_t)NP * DM;              // [1, 8, 4096, 2048]

    float *Qp, *Kp, *Vp, *Cp, *Tp;
    cudaGetSymbolAddress((void**)&Qp, g_Q);
    cudaGetSymbolAddress((void**)&Kp, g_K);
    cudaGetSymbolAddress((void**)&Vp, g_V);
    cudaGetSymbolAddress((void**)&Cp, g_ctx);
    cudaGetSymbolAddress((void**)&Tp, g_tmp);

    // Phase 1: Q/K/V projections + attn zero-fill + batch prep, one launch
    p1_kernel<<<256 + 4096 + 1, 256>>>(protein, ligand, bp_raw, bl_raw,
                                       Wq, bq, Wk, bk, Wv, bv,
                                       Qp, Kp, Vp, (float4*)attn);

    // Scores + softmax fused, then context (tensor cores throughout)
    score_sm<<<dim3(MAXT, NH), 256>>>(Qp, Kp, attn);
    ctx_mma<<<dim3(MAXT, NH), 256>>>(attn, Vp, Cp);

    // Output projection + residual, then LayerNorm
    gemm_tf32<<<dim3(DM / 128, NP / 128), 256>>>(Cp, Wo, bo, protein, Tp);
    ln_kernel<<<NP / 8, 256>>>(Tp, gamma, beta, out);
}

// round 12
// speedup vs baseline: 13.3693x; 1.2675x over previous
#include <cuda_runtime.h>
#include <cuda_bf16.h>
#include <cstdint>

#define NP 4096
#define NL 2048
#define DM 512
#define NH 8
#define DK 64
#define NB 16
#define MAXT 80   // max row tiles: 4096/64 + 16

// Scratch (allocation-free rule: __device__ globals)
__device__ float g_Q[NP * DM];
__device__ float g_K[NL * DM];
__device__ float g_V[NL * DM];
__device__ float g_ctx[NP * DM];
__device__ float g_tmp[NP * DM];
__device__ int   g_bp[NP];
__device__ int   g_bl[NL];
__device__ int   g_pstart[NB], g_pend[NB];
__device__ int   g_lstart[NB], g_lend[NB];
__device__ int   g_tile_b[MAXT], g_tile_r[MAXT];

__device__ __forceinline__ float to_tf32(float x) {
    float y;
    asm("cvt.rna.tf32.f32 %0, %1;" : "=f"(y) : "f"(x));
    return y;
}

#define MMA_TF32(d, a, b) \
    asm volatile("mma.sync.aligned.m16n8k8.row.col.f32.tf32.tf32.f32 " \
        "{%0,%1,%2,%3}, {%4,%5,%6,%7}, {%8,%9}, {%0,%1,%2,%3};" \
        : "+f"((d)[0]), "+f"((d)[1]), "+f"((d)[2]), "+f"((d)[3]) \
        : "r"((a)[0]), "r"((a)[1]), "r"((a)[2]), "r"((a)[3]), \
          "r"((b)[0]), "r"((b)[1]))

__device__ __forceinline__ void cp16(void* sdst, const void* gsrc) {
    uint32_t s = (uint32_t)__cvta_generic_to_shared(sdst);
    asm volatile("cp.async.ca.shared.global [%0], [%1], 16;" :: "r"(s), "l"(gsrc) : "memory");
}
#define CP_COMMIT() asm volatile("cp.async.commit_group;" ::: "memory")
#define CP_WAIT(n)  asm volatile("cp.async.wait_group %0;" :: "n"(n) : "memory")

// ---------------------------------------------------------------------------
// tf32 mma GEMM tile, cp.async double-buffered.
// Y[128,128] = X[128,K] W[128,K]^T + bias (+res). 8 warps (2x4), warp 64x32.
// K-chunk 16, pad 20 floats (80B: 16B-aligned rows, conflict-free fragments).
// fp32 staged raw; tensor core rounds to tf32 internally (Ampere+ semantics).
// ---------------------------------------------------------------------------
#define GK   16
#define GPAD 20

__device__ __forceinline__ void gemm_tile(const float* __restrict__ X,
                                          const float* __restrict__ W,
                                          const float* __restrict__ bias,
                                          const float* __restrict__ res,
                                          float* __restrict__ Y,
                                          int row0, int col0)
{
    __shared__ __align__(16) float Xs[2][128 * GPAD];
    __shared__ __align__(16) float Ws[2][128 * GPAD];

    const int t = threadIdx.x;
    const int lane = t & 31, w = t >> 5;
    const int wm = w >> 2, wn = w & 3;
    const int m0 = wm * 64, n0 = wn * 32;
    const int gid = lane >> 2, q4 = lane & 3;

    float d[4][4][4] = {};

    // stage chunk kc into buffer buf: 128 rows x 16 floats = 512 float4 per matrix
    auto stage = [&](int buf, int k0) {
        #pragma unroll
        for (int j = 0; j < 2; j++) {
            const int f = t + j * 256;
            const int r = f >> 2, q = (f & 3) * 4;
            cp16(&Xs[buf][r * GPAD + q], X + (size_t)(row0 + r) * DM + k0 + q);
            cp16(&Ws[buf][r * GPAD + q], W + (size_t)(col0 + r) * DM + k0 + q);
        }
    };

    const int NCH = DM / GK;   // 32 chunks
    stage(0, 0);
    CP_COMMIT();

    for (int kc = 0; kc < NCH; kc++) {
        const int buf = kc & 1;
        if (kc + 1 < NCH) {
            stage(buf ^ 1, (kc + 1) * GK);
            CP_COMMIT();
            CP_WAIT(1);            // current chunk's group complete
        } else {
            CP_WAIT(0);
        }
        __syncthreads();           // staged data visible to all warps

        #pragma unroll
        for (int kk = 0; kk < GK; kk += 8) {
            uint32_t a[4][4], b[4][2];
            #pragma unroll
            for (int mt = 0; mt < 4; mt++) {
                const int rb = m0 + mt * 16 + gid;
                a[mt][0] = __float_as_uint(Xs[buf][rb * GPAD + kk + q4]);
                a[mt][1] = __float_as_uint(Xs[buf][(rb + 8) * GPAD + kk + q4]);
                a[mt][2] = __float_as_uint(Xs[buf][rb * GPAD + kk + q4 + 4]);
                a[mt][3] = __float_as_uint(Xs[buf][(rb + 8) * GPAD + kk + q4 + 4]);
            }
            #pragma unroll
            for (int nt = 0; nt < 4; nt++) {
                const int nb = n0 + nt * 8 + gid;
                b[nt][0] = __float_as_uint(Ws[buf][nb * GPAD + kk + q4]);
                b[nt][1] = __float_as_uint(Ws[buf][nb * GPAD + kk + q4 + 4]);
            }
            #pragma unroll
            for (int mt = 0; mt < 4; mt++)
                #pragma unroll
                for (int nt = 0; nt < 4; nt++)
                    MMA_TF32(d[mt][nt], a[mt], b[nt]);
        }
        __syncthreads();           // WAR: buffer reuse safe for next stage
    }

    #pragma unroll
    for (int mt = 0; mt < 4; mt++) {
        #pragma unroll
        for (int nt = 0; nt < 4; nt++) {
            const int r1 = row0 + m0 + mt * 16 + gid;
            const int c  = col0 + n0 + nt * 8 + q4 * 2;
            const float b0 = bias[c], b1 = bias[c + 1];
            float2 o0 = make_float2(d[mt][nt][0] + b0, d[mt][nt][1] + b1);
            float2 o1 = make_float2(d[mt][nt][2] + b0, d[mt][nt][3] + b1);
            if (res) {
                const float2 r0v = *reinterpret_cast<const float2*>(res + (size_t)r1 * DM + c);
                const float2 r1v = *reinterpret_cast<const float2*>(res + (size_t)(r1 + 8) * DM + c);
                o0.x += r0v.x; o0.y += r0v.y;
                o1.x += r1v.x; o1.y += r1v.y;
            }
            *reinterpret_cast<float2*>(Y + (size_t)r1 * DM + c) = o0;
            *reinterpret_cast<float2*>(Y + (size_t)(r1 + 8) * DM + c) = o1;
        }
    }
}

// ---------------------------------------------------------------------------
// Phase 1 fused kernel:
//   CTAs [0,256)        : Q/K/V projections (tensor-bound)
//   CTAs [256, 256+4096): zero-fill of attn output (DRAM-bound)
//   CTA  4352           : batch prep (dtype normalize, ranges, tile worklist)
// ---------------------------------------------------------------------------
__global__ void __launch_bounds__(256) p1_kernel(
    const float* __restrict__ protein, const float* __restrict__ ligand,
    const int* __restrict__ bpraw, const int* __restrict__ blraw,
    const float* __restrict__ Wq, const float* __restrict__ bq,
    const float* __restrict__ Wk, const float* __restrict__ bk,
    const float* __restrict__ Wv, const float* __restrict__ bv,
    float* __restrict__ Qp, float* __restrict__ Kp, float* __restrict__ Vp,
    float4* __restrict__ attn4)
{
    const int bx = blockIdx.x;
    const int t = threadIdx.x;
    if (bx < 256) {
        const float *X, *W, *bias; float* Y; int lb;
        if (bx < 128)      { X = protein; W = Wq; bias = bq; Y = Qp; lb = bx; }
        else if (bx < 192) { X = ligand;  W = Wk; bias = bk; Y = Kp; lb = bx - 128; }
        else               { X = ligand;  W = Wv; bias = bv; Y = Vp; lb = bx - 192; }
        gemm_tile(X, W, bias, nullptr, Y, (lb >> 2) * 128, (lb & 3) * 128);
    } else if (bx < 256 + 4096) {
        const int z = bx - 256;                 // 0..4095, 4096 float4 each
        const float4 zero4 = make_float4(0.f, 0.f, 0.f, 0.f);
        const int base = z * 4096 + t;
        #pragma unroll
        for (int i = 0; i < 16; i++) attn4[base + i * 256] = zero4;
    } else {
        // prep: batch arrays -> int32, ranges, tile worklist.
        const int is32p = (bpraw[NP - 1] != 0);
        const int is32l = (blraw[NL - 1] != 0);
        if (t < NB) { g_pstart[t] = 0; g_pend[t] = 0; g_lstart[t] = 0; g_lend[t] = 0; }
        for (int i = t; i < NP; i += 256) g_bp[i] = is32p ? bpraw[i] : bpraw[2 * i];
        for (int i = t; i < NL; i += 256) g_bl[i] = is32l ? blraw[i] : blraw[2 * i];
        __syncthreads();
        for (int i = t; i < NP; i += 256) {
            const int b = g_bp[i];
            if (i == 0 || g_bp[i - 1] != b) g_pstart[b] = i;
            if (i == NP - 1 || g_bp[i + 1] != b) g_pend[b] = i + 1;
        }
        for (int i = t; i < NL; i += 256) {
            const int b = g_bl[i];
            if (i == 0 || g_bl[i - 1] != b) g_lstart[b] = i;
            if (i == NL - 1 || g_bl[i + 1] != b) g_lend[b] = i + 1;
        }
        __syncthreads();
        if (t == 0) {
            int idx = 0;
            for (int b = 0; b < NB; b++)
                for (int r = g_pstart[b]; r < g_pend[b]; r += 64) {
                    g_tile_b[idx] = b; g_tile_r[idx] = r; idx++;
                }
            for (; idx < MAXT; idx++) g_tile_b[idx] = -1;
        }
    }
}

// Standalone GEMM wrapper (output projection).
__global__ void __launch_bounds__(256) gemm_tf32(const float* __restrict__ X,
                                                 const float* __restrict__ W,
                                                 const float* __restrict__ bias,
                                                 const float* __restrict__ res,
                                                 float* __restrict__ Y)
{
    gemm_tile(X, W, bias, res, Y, blockIdx.y * 128, blockIdx.x * 128);
}

// ---------------------------------------------------------------------------
// Scores + softmax fused: per (row-tile 64, head).
// Pass A: S = (Q*0.125) . K^T via tf32 mma, raw scores -> attn gmem (L2 hot).
// Pass B (in-kernel): warp-per-8-rows max -> exp(store) -> scale. Single exp.
// ---------------------------------------------------------------------------
#define SPAD 68

__global__ void __launch_bounds__(256) score_sm(const float* __restrict__ Q,
                                                const float* __restrict__ Km,
                                                float* __restrict__ attn)
{
    const int b = g_tile_b[blockIdx.x];
    if (b < 0) return;
    const int r0 = g_tile_r[blockIdx.x];
    const int nr = min(64, g_pend[b] - r0);
    const int l0 = g_lstart[b], l1 = g_lend[b];
    const int h  = blockIdx.y;

    __shared__ __align__(16) float Qs[64 * SPAD];   // [row][k], prescaled
    __shared__ __align__(16) float Ks[64 * SPAD];   // [key][k]

    const int t = threadIdx.x;
    const int lane = t & 31, w = t >> 5;
    const int wm = w >> 2, wn = w & 3;
    const int m0 = wm * 32, n0 = wn * 16;
    const int gid = lane >> 2, q4 = lane & 3;

    // Vectorized Q staging: 64 rows x 16 float4
    #pragma unroll
    for (int i = t; i < 1024; i += 256) {
        const int row = i >> 4, q = (i & 15) * 4;
        float4 v = make_float4(0.f, 0.f, 0.f, 0.f);
        if (row < nr)
            v = *reinterpret_cast<const float4*>(Q + (size_t)(r0 + row) * DM + h * 64 + q);
        v.x = to_tf32(v.x * 0.125f); v.y = to_tf32(v.y * 0.125f);
        v.z = to_tf32(v.z * 0.125f); v.w = to_tf32(v.w * 0.125f);
        *reinterpret_cast<float4*>(&Qs[row * SPAD + q]) = v;
    }

    for (int lc = l0; lc < l1; lc += 64) {
        #pragma unroll
        for (int i = t; i < 1024; i += 256) {
            const int col = i >> 4, q = (i & 15) * 4;
            float4 v = make_float4(0.f, 0.f, 0.f, 0.f);
            if (lc + col < l1)
                v = *reinterpret_cast<const float4*>(Km + (size_t)(lc + col) * DM + h * 64 + q);
            v.x = to_tf32(v.x); v.y = to_tf32(v.y); v.z = to_tf32(v.z); v.w = to_tf32(v.w);
            *reinterpret_cast<float4*>(&Ks[col * SPAD + q]) = v;
        }
        __syncthreads();

        float d[2][2][4] = {};
        #pragma unroll
        for (int kk = 0; kk < 64; kk += 8) {
            uint32_t a[2][4], bb[2][2];
            #pragma unroll
            for (int mt = 0; mt < 2; mt++) {
                const int rb = m0 + mt * 16 + gid;
                a[mt][0] = __float_as_uint(Qs[rb * SPAD + kk + q4]);
                a[mt][1] = __float_as_uint(Qs[(rb + 8) * SPAD + kk + q4]);
                a[mt][2] = __float_as_uint(Qs[rb * SPAD + kk + q4 + 4]);
                a[mt][3] = __float_as_uint(Qs[(rb + 8) * SPAD + kk + q4 + 4]);
            }
            #pragma unroll
            for (int nt = 0; nt < 2; nt++) {
                const int nb = n0 + nt * 8 + gid;
                bb[nt][0] = __float_as_uint(Ks[nb * SPAD + kk + q4]);
                bb[nt][1] = __float_as_uint(Ks[nb * SPAD + kk + q4 + 4]);
            }
            #pragma unroll
            for (int mt = 0; mt < 2; mt++)
                #pragma unroll
                for (int nt = 0; nt < 2; nt++)
                    MMA_TF32(d[mt][nt], a[mt], bb[nt]);
        }

        #pragma unroll
        for (int mt = 0; mt < 2; mt++) {
            #pragma unroll
            for (int nt = 0; nt < 2; nt++) {
                const int rr = m0 + mt * 16 + gid;
                const int c  = lc + n0 + nt * 8 + q4 * 2;
                float* a0 = attn + ((size_t)h * NP + (r0 + rr)) * NL;
                float* a1 = a0 + 8 * NL;
                if (rr < nr) {
                    if (c < l1)     a0[c]     = d[mt][nt][0];
                    if (c + 1 < l1) a0[c + 1] = d[mt][nt][1];
                }
                if (rr + 8 < nr) {
                    if (c < l1)     a1[c]     = d[mt][nt][2];
                    if (c + 1 < l1) a1[c + 1] = d[mt][nt][3];
                }
            }
        }
        __syncthreads();
    }

    // Pass B: softmax over [l0, l1) per row; raw scores are L2-hot.
    #pragma unroll
    for (int rr8 = 0; rr8 < 8; rr8++) {
        const int row = w * 8 + rr8;
        if (row >= nr) continue;
        float* arow = attn + ((size_t)h * NP + (r0 + row)) * NL;

        float mx = -1e30f;
        for (int l = l0 + lane; l < l1; l += 32) mx = fmaxf(mx, arow[l]);
        #pragma unroll
        for (int o = 16; o; o >>= 1) mx = fmaxf(mx, __shfl_xor_sync(0xffffffffu, mx, o));

        float sum = 0.f;
        for (int l = l0 + lane; l < l1; l += 32) {
            const float e = __expf(arow[l] - mx);
            arow[l] = e;
            sum += e;
        }
        #pragma unroll
        for (int o = 16; o; o >>= 1) sum += __shfl_xor_sync(0xffffffffu, sum, o);
        const float inv = 1.f / sum;

        for (int l = l0 + lane; l < l1; l += 32) arow[l] *= inv;
    }
}

// ---------------------------------------------------------------------------
// Context via tf32 mma: per (row-tile 64, head). C = P . V over key range.
// Writes scrambled layout (h*NP+p)*64 + d.
// ---------------------------------------------------------------------------
#define VPAD 72

__global__ void __launch_bounds__(256) ctx_mma(const float* __restrict__ attn,
                                               const float* __restrict__ Vm,
                                               float* __restrict__ ctx)
{
    const int b = g_tile_b[blockIdx.x];
    if (b < 0) return;
    const int r0 = g_tile_r[blockIdx.x];
    const int nr = min(64, g_pend[b] - r0);
    const int l0 = g_lstart[b], l1 = g_lend[b];
    const int h  = blockIdx.y;

    __shared__ __align__(16) float Ps[64 * SPAD];   // [row][l]
    __shared__ __align__(16) float Vs[64 * VPAD];   // [l][d]

    const int t = threadIdx.x;
    const int lane = t & 31, w = t >> 5;
    const int wm = w >> 2, wn = w & 3;
    const int m0 = wm * 32, n0 = wn * 16;
    const int gid = lane >> 2, q4 = lane & 3;

    float d[2][2][4] = {};

    for (int lc = l0; lc < l1; lc += 64) {
        // Ps staging scalar (lc alignment unknown)
        for (int i = t; i < 64 * 64; i += 256) {
            const int row = i >> 6, li = i & 63;
            Ps[row * SPAD + li] = (row < nr && lc + li < l1)
                ? to_tf32(attn[((size_t)h * NP + (r0 + row)) * NL + lc + li]) : 0.f;
        }
        // Vs staging vectorized
        #pragma unroll
        for (int i = t; i < 1024; i += 256) {
            const int l = i >> 4, q = (i & 15) * 4;
            float4 v = make_float4(0.f, 0.f, 0.f, 0.f);
            if (lc + l < l1)
                v = *reinterpret_cast<const float4*>(Vm + (size_t)(lc + l) * DM + h * 64 + q);
            v.x = to_tf32(v.x); v.y = to_tf32(v.y); v.z = to_tf32(v.z); v.w = to_tf32(v.w);
            *reinterpret_cast<float4*>(&Vs[l * VPAD + q]) = v;
        }
        __syncthreads();

        #pragma unroll
        for (int kk = 0; kk < 64; kk += 8) {
            uint32_t a[2][4], bb[2][2];
            #pragma unroll
            for (int mt = 0; mt < 2; mt++) {
                const int rb = m0 + mt * 16 + gid;
                a[mt][0] = __float_as_uint(Ps[rb * SPAD + kk + q4]);
                a[mt][1] = __float_as_uint(Ps[(rb + 8) * SPAD + kk + q4]);
                a[mt][2] = __float_as_uint(Ps[rb * SPAD + kk + q4 + 4]);
                a[mt][3] = __float_as_uint(Ps[(rb + 8) * SPAD + kk + q4 + 4]);
            }
            #pragma unroll
            for (int nt = 0; nt < 2; nt++) {
                const int nb = n0 + nt * 8 + gid;   // d-column
                bb[nt][0] = __float_as_uint(Vs[(kk + q4) * VPAD + nb]);
                bb[nt][1] = __float_as_uint(Vs[(kk + q4 + 4) * VPAD + nb]);
            }
            #pragma unroll
            for (int mt = 0; mt < 2; mt++)
                #pragma unroll
                for (int nt = 0; nt < 2; nt++)
                    MMA_TF32(d[mt][nt], a[mt], bb[nt]);
        }
        __syncthreads();
    }

    #pragma unroll
    for (int mt = 0; mt < 2; mt++) {
        #pragma unroll
        for (int nt = 0; nt < 2; nt++) {
            const int rr = m0 + mt * 16 + gid;
            const int c  = n0 + nt * 8 + q4 * 2;
            if (rr < nr) {
                float* o = ctx + ((size_t)h * NP + (r0 + rr)) * 64;
                o[c] = d[mt][nt][0]; o[c + 1] = d[mt][nt][1];
            }
            if (rr + 8 < nr) {
                float* o = ctx + ((size_t)h * NP + (r0 + rr + 8)) * 64;
                o[c] = d[mt][nt][2]; o[c + 1] = d[mt][nt][3];
            }
        }
    }
}

// ---------------------------------------------------------------------------
// LayerNorm: warp per row over 512 features.
// ---------------------------------------------------------------------------
__global__ void ln_kernel(const float* __restrict__ X,
                          const float* __restrict__ gamma,
                          const float* __restrict__ beta,
                          float* __restrict__ out)
{
    const int row  = blockIdx.x * 8 + (threadIdx.x >> 5);
    const int lane = threadIdx.x & 31;
    const float* xr = X + (size_t)row * DM;

    float v[16];
    float s = 0.f;
    #pragma unroll
    for (int i = 0; i < 16; i++) { v[i] = xr[lane + i * 32]; s += v[i]; }
    #pragma unroll
    for (int o = 16; o; o >>= 1) s += __shfl_xor_sync(0xffffffffu, s, o);
    const float mu = s * (1.f / 512.f);

    float q = 0.f;
    #pragma unroll
    for (int i = 0; i < 16; i++) { const float d = v[i] - mu; q += d * d; }
    #pragma unroll
    for (int o = 16; o; o >>= 1) q += __shfl_xor_sync(0xffffffffu, q, o);
    const float rstd = rsqrtf(q * (1.f / 512.f) + 1e-5f);

    #pragma unroll
    for (int i = 0; i < 16; i++) {
        const int c = lane + i * 32;
        out[(size_t)row * DM + c] = (v[i] - mu) * rstd * gamma[c] + beta[c];
    }
}

// ---------------------------------------------------------------------------
extern "C" void kernel_launch(void* const* d_in, const int* in_sizes, int n_in,
                              void* d_out, int out_size)
{
    const float* protein = (const float*)d_in[0];
    const float* ligand  = (const float*)d_in[1];
    const int* bp_raw    = (const int*)d_in[2];
    const int* bl_raw    = (const int*)d_in[3];
    const float* Wq = (const float*)d_in[4];
    const float* bq = (const float*)d_in[5];
    const float* Wk = (const float*)d_in[6];
    const float* bk = (const float*)d_in[7];
    const float* Wv = (const float*)d_in[8];
    const float* bv = (const float*)d_in[9];
    const float* Wo = (const float*)d_in[10];
    const float* bo = (const float*)d_in[11];
    const float* gamma = (const float*)d_in[12];
    const float* beta  = (const float*)d_in[13];

    float* out  = (float*)d_out;                      // [4096, 512]
    float* attn = out + (size_t)NP * DM;              // [1, 8, 4096, 2048]

    float *Qp, *Kp, *Vp, *Cp, *Tp;
    cudaGetSymbolAddress((void**)&Qp, g_Q);
    cudaGetSymbolAddress((void**)&Kp, g_K);
    cudaGetSymbolAddress((void**)&Vp, g_V);
    cudaGetSymbolAddress((void**)&Cp, g_ctx);
    cudaGetSymbolAddress((void**)&Tp, g_tmp);

    // Phase 1: Q/K/V projections + attn zero-fill + batch prep, one launch
    p1_kernel<<<256 + 4096 + 1, 256>>>(protein, ligand, bp_raw, bl_raw,
                                       Wq, bq, Wk, bk, Wv, bv,
                                       Qp, Kp, Vp, (float4*)attn);

    // Scores + softmax fused, then context (tensor cores throughout)
    score_sm<<<dim3(MAXT, NH), 256>>>(Qp, Kp, attn);
    ctx_mma<<<dim3(MAXT, NH), 256>>>(attn, Vp, Cp);

    // Output projection + residual, then LayerNorm
    gemm_tf32<<<dim3(DM / 128, NP / 128), 256>>>(Cp, Wo, bo, protein, Tp);
    ln_kernel<<<NP / 8, 256>>>(Tp, gamma, beta, out);
}

// round 13
// speedup vs baseline: 13.3844x; 1.0011x over previous
#include <cuda_runtime.h>
#include <cuda_bf16.h>
#include <cstdint>

#define NP 4096
#define NL 2048
#define DM 512
#define NH 8
#define DK 64
#define NB 16
#define MAXT 80   // max row tiles: 4096/64 + 16

// Scratch (allocation-free rule: __device__ globals)
__device__ float g_Q[NP * DM];
__device__ float g_K[NL * DM];
__device__ float g_V[NL * DM];
__device__ float g_ctx[NP * DM];
__device__ float g_tmp[NP * DM];
__device__ int   g_bp[NP];
__device__ int   g_bl[NL];
__device__ int   g_pstart[NB], g_pend[NB];
__device__ int   g_lstart[NB], g_lend[NB];
__device__ int   g_tile_b[MAXT], g_tile_r[MAXT];

__device__ __forceinline__ float to_tf32(float x) {
    float y;
    asm("cvt.rna.tf32.f32 %0, %1;" : "=f"(y) : "f"(x));
    return y;
}

#define MMA_TF32(d, a, b) \
    asm volatile("mma.sync.aligned.m16n8k8.row.col.f32.tf32.tf32.f32 " \
        "{%0,%1,%2,%3}, {%4,%5,%6,%7}, {%8,%9}, {%0,%1,%2,%3};" \
        : "+f"((d)[0]), "+f"((d)[1]), "+f"((d)[2]), "+f"((d)[3]) \
        : "r"((a)[0]), "r"((a)[1]), "r"((a)[2]), "r"((a)[3]), \
          "r"((b)[0]), "r"((b)[1]))

__device__ __forceinline__ void cp16(void* sdst, const void* gsrc) {
    uint32_t s = (uint32_t)__cvta_generic_to_shared(sdst);
    asm volatile("cp.async.ca.shared.global [%0], [%1], 16;" :: "r"(s), "l"(gsrc) : "memory");
}
#define CP_COMMIT() asm volatile("cp.async.commit_group;" ::: "memory")
#define CP_WAIT(n)  asm volatile("cp.async.wait_group %0;" :: "n"(n) : "memory")

// ---------------------------------------------------------------------------
// tf32 mma GEMM tile, cp.async double-buffered.
// Y[64,128] = X[64,K] W[128,K]^T + bias (+res). 8 warps (2x4), warp 32x32.
// Smaller tile -> 3-4 CTAs/SM co-resident for cross-CTA latency hiding.
// ---------------------------------------------------------------------------
#define GK   16
#define GPAD 20

__device__ __forceinline__ void gemm_tile(const float* __restrict__ X,
                                          const float* __restrict__ W,
                                          const float* __restrict__ bias,
                                          const float* __restrict__ res,
                                          float* __restrict__ Y,
                                          int row0, int col0)
{
    __shared__ __align__(16) float Xs[2][64 * GPAD];
    __shared__ __align__(16) float Ws[2][128 * GPAD];

    const int t = threadIdx.x;
    const int lane = t & 31, w = t >> 5;
    const int wm = w >> 2, wn = w & 3;          // 2 x 4 warp grid
    const int m0 = wm * 32, n0 = wn * 32;       // warp tile 32x32
    const int gid = lane >> 2, q4 = lane & 3;

    float d[2][4][4] = {};

    // stage chunk into buf: X 64x16 = 256 float4, W 128x16 = 512 float4
    auto stage = [&](int buf, int k0) {
        #pragma unroll
        for (int j = 0; j < 3; j++) {
            const int f = t + j * 256;           // 0..767
            if (f < 256) {
                const int r = f >> 2, q = (f & 3) * 4;
                cp16(&Xs[buf][r * GPAD + q], X + (size_t)(row0 + r) * DM + k0 + q);
            } else {
                const int g = f - 256;
                const int r = g >> 2, q = (g & 3) * 4;
                cp16(&Ws[buf][r * GPAD + q], W + (size_t)(col0 + r) * DM + k0 + q);
            }
        }
    };

    const int NCH = DM / GK;   // 32 chunks
    stage(0, 0);
    CP_COMMIT();

    for (int kc = 0; kc < NCH; kc++) {
        const int buf = kc & 1;
        if (kc + 1 < NCH) {
            stage(buf ^ 1, (kc + 1) * GK);
            CP_COMMIT();
            CP_WAIT(1);
        } else {
            CP_WAIT(0);
        }
        __syncthreads();

        #pragma unroll
        for (int kk = 0; kk < GK; kk += 8) {
            uint32_t a[2][4], b[4][2];
            #pragma unroll
            for (int mt = 0; mt < 2; mt++) {
                const int rb = m0 + mt * 16 + gid;
                a[mt][0] = __float_as_uint(Xs[buf][rb * GPAD + kk + q4]);
                a[mt][1] = __float_as_uint(Xs[buf][(rb + 8) * GPAD + kk + q4]);
                a[mt][2] = __float_as_uint(Xs[buf][rb * GPAD + kk + q4 + 4]);
                a[mt][3] = __float_as_uint(Xs[buf][(rb + 8) * GPAD + kk + q4 + 4]);
            }
            #pragma unroll
            for (int nt = 0; nt < 4; nt++) {
                const int nb = n0 + nt * 8 + gid;
                b[nt][0] = __float_as_uint(Ws[buf][nb * GPAD + kk + q4]);
                b[nt][1] = __float_as_uint(Ws[buf][nb * GPAD + kk + q4 + 4]);
            }
            #pragma unroll
            for (int mt = 0; mt < 2; mt++)
                #pragma unroll
                for (int nt = 0; nt < 4; nt++)
                    MMA_TF32(d[mt][nt], a[mt], b[nt]);
        }
        __syncthreads();
    }

    #pragma unroll
    for (int mt = 0; mt < 2; mt++) {
        #pragma unroll
        for (int nt = 0; nt < 4; nt++) {
            const int r1 = row0 + m0 + mt * 16 + gid;
            const int c  = col0 + n0 + nt * 8 + q4 * 2;
            const float b0 = bias[c], b1 = bias[c + 1];
            float2 o0 = make_float2(d[mt][nt][0] + b0, d[mt][nt][1] + b1);
            float2 o1 = make_float2(d[mt][nt][2] + b0, d[mt][nt][3] + b1);
            if (res) {
                const float2 r0v = *reinterpret_cast<const float2*>(res + (size_t)r1 * DM + c);
                const float2 r1v = *reinterpret_cast<const float2*>(res + (size_t)(r1 + 8) * DM + c);
                o0.x += r0v.x; o0.y += r0v.y;
                o1.x += r1v.x; o1.y += r1v.y;
            }
            *reinterpret_cast<float2*>(Y + (size_t)r1 * DM + c) = o0;
            *reinterpret_cast<float2*>(Y + (size_t)(r1 + 8) * DM + c) = o1;
        }
    }
}

// ---------------------------------------------------------------------------
// Phase 1 fused kernel:
//   CTAs [0,512)        : Q/K/V projections (64x128 tiles; Q:256, K:128, V:128)
//   CTAs [512, 512+4096): zero-fill of attn output (DRAM-bound)
//   CTA  4608           : batch prep (dtype normalize, ranges, tile worklist)
// ---------------------------------------------------------------------------
__global__ void __launch_bounds__(256) p1_kernel(
    const float* __restrict__ protein, const float* __restrict__ ligand,
    const int* __restrict__ bpraw, const int* __restrict__ blraw,
    const float* __restrict__ Wq, const float* __restrict__ bq,
    const float* __restrict__ Wk, const float* __restrict__ bk,
    const float* __restrict__ Wv, const float* __restrict__ bv,
    float* __restrict__ Qp, float* __restrict__ Kp, float* __restrict__ Vp,
    float4* __restrict__ attn4)
{
    const int bx = blockIdx.x;
    const int t = threadIdx.x;
    if (bx < 512) {
        const float *X, *W, *bias; float* Y; int lb;
        if (bx < 256)      { X = protein; W = Wq; bias = bq; Y = Qp; lb = bx; }
        else if (bx < 384) { X = ligand;  W = Wk; bias = bk; Y = Kp; lb = bx - 256; }
        else               { X = ligand;  W = Wv; bias = bv; Y = Vp; lb = bx - 384; }
        gemm_tile(X, W, bias, nullptr, Y, (lb >> 2) * 64, (lb & 3) * 128);
    } else if (bx < 512 + 4096) {
        const int z = bx - 512;                 // 0..4095, 4096 float4 each
        const float4 zero4 = make_float4(0.f, 0.f, 0.f, 0.f);
        const int base = z * 4096 + t;
        #pragma unroll
        for (int i = 0; i < 16; i++) attn4[base + i * 256] = zero4;
    } else {
        // prep: batch arrays -> int32, ranges, tile worklist.
        const int is32p = (bpraw[NP - 1] != 0);
        const int is32l = (blraw[NL - 1] != 0);
        if (t < NB) { g_pstart[t] = 0; g_pend[t] = 0; g_lstart[t] = 0; g_lend[t] = 0; }
        for (int i = t; i < NP; i += 256) g_bp[i] = is32p ? bpraw[i] : bpraw[2 * i];
        for (int i = t; i < NL; i += 256) g_bl[i] = is32l ? blraw[i] : blraw[2 * i];
        __syncthreads();
        for (int i = t; i < NP; i += 256) {
            const int b = g_bp[i];
            if (i == 0 || g_bp[i - 1] != b) g_pstart[b] = i;
            if (i == NP - 1 || g_bp[i + 1] != b) g_pend[b] = i + 1;
        }
        for (int i = t; i < NL; i += 256) {
            const int b = g_bl[i];
            if (i == 0 || g_bl[i - 1] != b) g_lstart[b] = i;
            if (i == NL - 1 || g_bl[i + 1] != b) g_lend[b] = i + 1;
        }
        __syncthreads();
        if (t == 0) {
            int idx = 0;
            for (int b = 0; b < NB; b++)
                for (int r = g_pstart[b]; r < g_pend[b]; r += 64) {
                    g_tile_b[idx] = b; g_tile_r[idx] = r; idx++;
                }
            for (; idx < MAXT; idx++) g_tile_b[idx] = -1;
        }
    }
}

// Standalone GEMM wrapper (output projection).
__global__ void __launch_bounds__(256) gemm_tf32(const float* __restrict__ X,
                                                 const float* __restrict__ W,
                                                 const float* __restrict__ bias,
                                                 const float* __restrict__ res,
                                                 float* __restrict__ Y)
{
    gemm_tile(X, W, bias, res, Y, blockIdx.y * 64, blockIdx.x * 128);
}

// ---------------------------------------------------------------------------
// Scores + softmax fused: per (row-tile 64, head).
// K chunks start at l0 & ~63 (16B-aligned cp.async sources); epilogue writes
// only columns in [l0, l1) — everything outside is exactly 0 (zero-fill).
// cp.async double-buffered K staging overlapped with MMA.
// ---------------------------------------------------------------------------
#define SPAD 68

__global__ void __launch_bounds__(256) score_sm(const float* __restrict__ Q,
                                                const float* __restrict__ Km,
                                                float* __restrict__ attn)
{
    const int b = g_tile_b[blockIdx.x];
    if (b < 0) return;
    const int r0 = g_tile_r[blockIdx.x];
    const int nr = min(64, g_pend[b] - r0);
    const int l0 = g_lstart[b], l1 = g_lend[b];
    const int h  = blockIdx.y;
    const int al0 = l0 & ~63;
    const int nch = (l1 - al0 + 63) >> 6;

    __shared__ __align__(16) float Qs[64 * SPAD];        // [row][k], prescaled
    __shared__ __align__(16) float Ks[2][64 * SPAD];     // [key][k] double buf

    const int t = threadIdx.x;
    const int lane = t & 31, w = t >> 5;
    const int wm = w >> 2, wn = w & 3;
    const int m0 = wm * 32, n0 = wn * 16;
    const int gid = lane >> 2, q4 = lane & 3;

    auto stageK = [&](int buf, int lc) {
        #pragma unroll
        for (int j = 0; j < 4; j++) {
            const int i = t + j * 256;               // 0..1023
            const int col = i >> 4, q = (i & 15) * 4;
            cp16(&Ks[buf][col * SPAD + q], Km + (size_t)(lc + col) * DM + h * 64 + q);
        }
    };

    stageK(0, al0);
    CP_COMMIT();

    // Q staging (scaled, tf32-rounded) overlaps with first K chunk in flight
    #pragma unroll
    for (int i = t; i < 1024; i += 256) {
        const int row = i >> 4, q = (i & 15) * 4;
        float4 v = make_float4(0.f, 0.f, 0.f, 0.f);
        if (row < nr)
            v = *reinterpret_cast<const float4*>(Q + (size_t)(r0 + row) * DM + h * 64 + q);
        v.x = to_tf32(v.x * 0.125f); v.y = to_tf32(v.y * 0.125f);
        v.z = to_tf32(v.z * 0.125f); v.w = to_tf32(v.w * 0.125f);
        *reinterpret_cast<float4*>(&Qs[row * SPAD + q]) = v;
    }

    for (int ch = 0; ch < nch; ch++) {
        const int lc = al0 + ch * 64;
        const int buf = ch & 1;
        if (ch + 1 < nch) {
            stageK(buf ^ 1, lc + 64);
            CP_COMMIT();
            CP_WAIT(1);
        } else {
            CP_WAIT(0);
        }
        __syncthreads();

        float d[2][2][4] = {};
        #pragma unroll
        for (int kk = 0; kk < 64; kk += 8) {
            uint32_t a[2][4], bb[2][2];
            #pragma unroll
            for (int mt = 0; mt < 2; mt++) {
                const int rb = m0 + mt * 16 + gid;
                a[mt][0] = __float_as_uint(Qs[rb * SPAD + kk + q4]);
                a[mt][1] = __float_as_uint(Qs[(rb + 8) * SPAD + kk + q4]);
                a[mt][2] = __float_as_uint(Qs[rb * SPAD + kk + q4 + 4]);
                a[mt][3] = __float_as_uint(Qs[(rb + 8) * SPAD + kk + q4 + 4]);
            }
            #pragma unroll
            for (int nt = 0; nt < 2; nt++) {
                const int nb = n0 + nt * 8 + gid;
                bb[nt][0] = __float_as_uint(Ks[buf][nb * SPAD + kk + q4]);
                bb[nt][1] = __float_as_uint(Ks[buf][nb * SPAD + kk + q4 + 4]);
            }
            #pragma unroll
            for (int mt = 0; mt < 2; mt++)
                #pragma unroll
                for (int nt = 0; nt < 2; nt++)
                    MMA_TF32(d[mt][nt], a[mt], bb[nt]);
        }

        #pragma unroll
        for (int mt = 0; mt < 2; mt++) {
            #pragma unroll
            for (int nt = 0; nt < 2; nt++) {
                const int rr = m0 + mt * 16 + gid;
                const int c  = lc + n0 + nt * 8 + q4 * 2;
                float* a0 = attn + ((size_t)h * NP + (r0 + rr)) * NL;
                float* a1 = a0 + 8 * NL;
                if (rr < nr) {
                    if (c >= l0 && c < l1)         a0[c]     = d[mt][nt][0];
                    if (c + 1 >= l0 && c + 1 < l1) a0[c + 1] = d[mt][nt][1];
                }
                if (rr + 8 < nr) {
                    if (c >= l0 && c < l1)         a1[c]     = d[mt][nt][2];
                    if (c + 1 >= l0 && c + 1 < l1) a1[c + 1] = d[mt][nt][3];
                }
            }
        }
        __syncthreads();
    }

    // Softmax over [l0, l1) per row; raw scores are L2-hot.
    #pragma unroll
    for (int rr8 = 0; rr8 < 8; rr8++) {
        const int row = w * 8 + rr8;
        if (row >= nr) continue;
        float* arow = attn + ((size_t)h * NP + (r0 + row)) * NL;

        float mx = -1e30f;
        for (int l = l0 + lane; l < l1; l += 32) mx = fmaxf(mx, arow[l]);
        #pragma unroll
        for (int o = 16; o; o >>= 1) mx = fmaxf(mx, __shfl_xor_sync(0xffffffffu, mx, o));

        float sum = 0.f;
        for (int l = l0 + lane; l < l1; l += 32) {
            const float e = __expf(arow[l] - mx);
            arow[l] = e;
            sum += e;
        }
        #pragma unroll
        for (int o = 16; o; o >>= 1) sum += __shfl_xor_sync(0xffffffffu, sum, o);
        const float inv = 1.f / sum;

        for (int l = l0 + lane; l < l1; l += 32) arow[l] *= inv;
    }
}

// ---------------------------------------------------------------------------
// Context via tf32 mma, cp.async double-buffered P and V staging.
// Chunks aligned to l0 & ~63: P columns outside [l0,l1) are exactly 0 in attn
// (zero-fill + guarded score writes), so they contribute nothing. P rows >= nr
// are left unstaged (garbage reaches only discarded D rows).
// Writes scrambled layout (h*NP+p)*64 + d.
// ---------------------------------------------------------------------------
#define VPAD 72

__global__ void __launch_bounds__(256) ctx_mma(const float* __restrict__ attn,
                                               const float* __restrict__ Vm,
                                               float* __restrict__ ctx)
{
    const int b = g_tile_b[blockIdx.x];
    if (b < 0) return;
    const int r0 = g_tile_r[blockIdx.x];
    const int nr = min(64, g_pend[b] - r0);
    const int l0 = g_lstart[b], l1 = g_lend[b];
    const int h  = blockIdx.y;
    const int al0 = l0 & ~63;
    const int nch = (l1 - al0 + 63) >> 6;

    __shared__ __align__(16) float Ps[2][64 * SPAD];   // [row][l]
    __shared__ __align__(16) float Vs[2][64 * VPAD];   // [l][d]

    const int t = threadIdx.x;
    const int lane = t & 31, w = t >> 5;
    const int wm = w >> 2, wn = w & 3;
    const int m0 = wm * 32, n0 = wn * 16;
    const int gid = lane >> 2, q4 = lane & 3;

    auto stagePV = [&](int buf, int lc) {
        #pragma unroll
        for (int j = 0; j < 4; j++) {
            const int i = t + j * 256;
            const int row = i >> 4, q = (i & 15) * 4;
            if (row < nr)
                cp16(&Ps[buf][row * SPAD + q],
                     attn + ((size_t)h * NP + (r0 + row)) * NL + lc + q);
        }
        #pragma unroll
        for (int j = 0; j < 4; j++) {
            const int i = t + j * 256;
            const int l = i >> 4, q = (i & 15) * 4;
            cp16(&Vs[buf][l * VPAD + q], Vm + (size_t)(lc + l) * DM + h * 64 + q);
        }
    };

    float d[2][2][4] = {};

    stagePV(0, al0);
    CP_COMMIT();

    for (int ch = 0; ch < nch; ch++) {
        const int buf = ch & 1;
        if (ch + 1 < nch) {
            stagePV(buf ^ 1, al0 + (ch + 1) * 64);
            CP_COMMIT();
            CP_WAIT(1);
        } else {
            CP_WAIT(0);
        }
        __syncthreads();

        #pragma unroll
        for (int kk = 0; kk < 64; kk += 8) {
            uint32_t a[2][4], bb[2][2];
            #pragma unroll
            for (int mt = 0; mt < 2; mt++) {
                const int rb = m0 + mt * 16 + gid;
                a[mt][0] = __float_as_uint(Ps[buf][rb * SPAD + kk + q4]);
                a[mt][1] = __float_as_uint(Ps[buf][(rb + 8) * SPAD + kk + q4]);
                a[mt][2] = __float_as_uint(Ps[buf][rb * SPAD + kk + q4 + 4]);
                a[mt][3] = __float_as_uint(Ps[buf][(rb + 8) * SPAD + kk + q4 + 4]);
            }
            #pragma unroll
            for (int nt = 0; nt < 2; nt++) {
                const int nb = n0 + nt * 8 + gid;   // d-column
                bb[nt][0] = __float_as_uint(Vs[buf][(kk + q4) * VPAD + nb]);
                bb[nt][1] = __float_as_uint(Vs[buf][(kk + q4 + 4) * VPAD + nb]);
            }
            #pragma unroll
            for (int mt = 0; mt < 2; mt++)
                #pragma unroll
                for (int nt = 0; nt < 2; nt++)
                    MMA_TF32(d[mt][nt], a[mt], bb[nt]);
        }
        __syncthreads();
    }

    #pragma unroll
    for (int mt = 0; mt < 2; mt++) {
        #pragma unroll
        for (int nt = 0; nt < 2; nt++) {
            const int rr = m0 + mt * 16 + gid;
            const int c  = n0 + nt * 8 + q4 * 2;
            if (rr < nr) {
                float* o = ctx + ((size_t)h * NP + (r0 + rr)) * 64;
                o[c] = d[mt][nt][0]; o[c + 1] = d[mt][nt][1];
            }
            if (rr + 8 < nr) {
                float* o = ctx + ((size_t)h * NP + (r0 + rr + 8)) * 64;
                o[c] = d[mt][nt][2]; o[c + 1] = d[mt][nt][3];
            }
        }
    }
}

// ---------------------------------------------------------------------------
// LayerNorm: warp per row over 512 features.
// ---------------------------------------------------------------------------
__global__ void ln_kernel(const float* __restrict__ X,
                          const float* __restrict__ gamma,
                          const float* __restrict__ beta,
                          float* __restrict__ out)
{
    const int row  = blockIdx.x * 8 + (threadIdx.x >> 5);
    const int lane = threadIdx.x & 31;
    const float* xr = X + (size_t)row * DM;

    float v[16];
    float s = 0.f;
    #pragma unroll
    for (int i = 0; i < 16; i++) { v[i] = xr[lane + i * 32]; s += v[i]; }
    #pragma unroll
    for (int o = 16; o; o >>= 1) s += __shfl_xor_sync(0xffffffffu, s, o);
    const float mu = s * (1.f / 512.f);

    float q = 0.f;
    #pragma unroll
    for (int i = 0; i < 16; i++) { const float d = v[i] - mu; q += d * d; }
    #pragma unroll
    for (int o = 16; o; o >>= 1) q += __shfl_xor_sync(0xffffffffu, q, o);
    const float rstd = rsqrtf(q * (1.f / 512.f) + 1e-5f);

    #pragma unroll
    for (int i = 0; i < 16; i++) {
        const int c = lane + i * 32;
        out[(size_t)row * DM + c] = (v[i] - mu) * rstd * gamma[c] + beta[c];
    }
}

// ---------------------------------------------------------------------------
extern "C" void kernel_launch(void* const* d_in, const int* in_sizes, int n_in,
                              void* d_out, int out_size)
{
    const float* protein = (const float*)d_in[0];
    const float* ligand  = (const float*)d_in[1];
    const int* bp_raw    = (const int*)d_in[2];
    const int* bl_raw    = (const int*)d_in[3];
    const float* Wq = (const float*)d_in[4];
    const float* bq = (const float*)d_in[5];
    const float* Wk = (const float*)d_in[6];
    const float* bk = (const float*)d_in[7];
    const float* Wv = (const float*)d_in[8];
    const float* bv = (const float*)d_in[9];
    const float* Wo = (const float*)d_in[10];
    const float* bo = (const float*)d_in[11];
    const float* gamma = (const float*)d_in[12];
    const float* beta  = (const float*)d_in[13];

    float* out  = (float*)d_out;                      // [4096, 512]
    float* attn = out + (size_t)NP * DM;              // [1, 8, 4096, 2048]

    float *Qp, *Kp, *Vp, *Cp, *Tp;
    cudaGetSymbolAddress((void**)&Qp, g_Q);
    cudaGetSymbolAddress((void**)&Kp, g_K);
    cudaGetSymbolAddress((void**)&Vp, g_V);
    cudaGetSymbolAddress((void**)&Cp, g_ctx);
    cudaGetSymbolAddress((void**)&Tp, g_tmp);

    // Phase 1: Q/K/V projections + attn zero-fill + batch prep, one launch
    p1_kernel<<<512 + 4096 + 1, 256>>>(protein, ligand, bp_raw, bl_raw,
                                       Wq, bq, Wk, bk, Wv, bv,
                                       Qp, Kp, Vp, (float4*)attn);

    // Scores + softmax fused, then context (tensor cores throughout)
    score_sm<<<dim3(MAXT, NH), 256>>>(Qp, Kp, attn);
    ctx_mma<<<dim3(MAXT, NH), 256>>>(attn, Vp, Cp);

    // Output projection + residual, then LayerNorm
    gemm_tf32<<<dim3(DM / 128, NP / 64), 256>>>(Cp, Wo, bo, protein, Tp);
    ln_kernel<<<NP / 8, 256>>>(Tp, gamma, beta, out);
}